// round 12
// baseline (speedup 1.0000x reference)
#include <cuda_runtime.h>
#include <cuda_bf16.h>

// ---------------------------------------------------------------------------
// WindowGrapherPyg fused kernel, R11 = R10 + 2-deep B-fragment prefetch ring.
// Barrier-free tensor-core GEMMs, (2 m-groups x 8 col-groups) warp grid,
// one-shot A split (tf32-hi in place + bf16 lo pairs in dead Gram buffer),
// W pre-split/pre-packed per-lane in global (L2-resident).
// Inner loop: 6 LDGs in flight (2 k-chunks ahead) covering ~250cyc L2 latency,
// plain LDS A operands, 18 MMAs per k-chunk, zero __syncthreads in GEMMs.
// m16n8k8 fragment map (lane = 4*g+tig):
//   A: a0=(g,k=tig) a1=(g+8,tig) a2=(g,tig+4) a3=(g+8,tig+4)
//   B: b0=(k=tig,n=g) b1=(k=tig+4,n=g)
//   D: c0=(g,2tig) c1=(g,2tig+1) c2=(g+8,2tig) c3=(g+8,2tig+1)
// ---------------------------------------------------------------------------

typedef unsigned long long u64;
typedef unsigned int u32;

namespace {
constexpr int Bc = 2, Cc = 192, Hc = 192, Wc = 192;
constexpr int WS = 8, NN = 64, KK = 9, HEADS = 8, DH = 24;
constexpr int NWH = Hc / WS, NWW = Wc / WS;         // 24 x 24
constexpr int WB = Bc * NWH * NWW;                  // 1152 windows
constexpr int STR = 196;                            // xw/Q/K/V row stride
constexpr int NT = 512;
constexpr int XW_FLOATS = NN * STR;                 // 12544
constexpr int NTILES = Cc / 8;                      // 24 n-tiles
constexpr int KCH = Cc / 8;                         // 24 k-chunks
constexpr int FRAG_PER_MAT = NTILES * KCH * 32;     // 18432 float4
constexpr int LOSTR = 100;                          // lo-pair row stride (u32)
constexpr int LO_U32 = NN * LOSTR;                  // 6400 (>= 4096 Gram alias)
constexpr size_t SMEM_BYTES =
    (size_t)(4 * XW_FLOATS + LO_U32 + NN) * sizeof(float) +
    (size_t)(NN * KK) * sizeof(int);                // 228,864 B
constexpr float INV_SQRT_DH = 0.20412414523193154f;
}

// Pre-packed tf32 hi/lo B fragments: [mat][ntile][kchunk][lane] float4.
__device__ float4 g_Wfrag[4 * FRAG_PER_MAT];

__device__ __forceinline__ u64 pack2f(float x, float y) {
  u64 r; asm("mov.b64 %0, {%1, %2};" : "=l"(r) : "f"(x), "f"(y)); return r;
}
__device__ __forceinline__ void fma2(u64& d, u64 a, u64 b) {
  asm("fma.rn.f32x2 %0, %1, %2, %0;" : "+l"(d) : "l"(a), "l"(b));
}
__device__ __forceinline__ float hsum2(u64 v) {
  float2 o; asm("mov.b64 {%0, %1}, %2;" : "=f"(o.x), "=f"(o.y) : "l"(v));
  return o.x + o.y;
}
__device__ __forceinline__ unsigned cvt_tf32(float f) {
  unsigned r; asm("cvt.rna.tf32.f32 %0, %1;" : "=r"(r) : "f"(f)); return r;
}
__device__ __forceinline__ void split_tf32(float f, unsigned& hi, unsigned& lo) {
  hi = cvt_tf32(f);
  lo = cvt_tf32(f - __uint_as_float(hi));
}
__device__ __forceinline__ void mma_tf32(float d[4], unsigned a0, unsigned a1,
                                         unsigned a2, unsigned a3,
                                         unsigned b0, unsigned b1) {
  asm("mma.sync.aligned.m16n8k8.row.col.f32.tf32.tf32.f32 "
      "{%0,%1,%2,%3}, {%4,%5,%6,%7}, {%8,%9}, {%0,%1,%2,%3};"
      : "+f"(d[0]), "+f"(d[1]), "+f"(d[2]), "+f"(d[3])
      : "r"(a0), "r"(a1), "r"(a2), "r"(a3), "r"(b0), "r"(b1));
}

// Prologue: pack W[k][n] into per-lane fragment float4s (see R8).
__global__ void pack_w_kernel(const float* __restrict__ w0,
                              const float* __restrict__ w1,
                              const float* __restrict__ w2,
                              const float* __restrict__ w3) {
  int i = blockIdx.x * blockDim.x + threadIdx.x;
  if (i >= 4 * FRAG_PER_MAT) return;
  int lane = i & 31;
  int t = i >> 5;
  int kc = t % KCH; t /= KCH;
  int ntile = t % NTILES;
  int mat = t / NTILES;
  const float* W = (mat == 0) ? w0 : (mat == 1) ? w1 : (mat == 2) ? w2 : w3;
  int n = ntile * 8 + (lane >> 2);
  int k0 = kc * 8 + (lane & 3);
  unsigned h0, l0, h1, l1;
  split_tf32(W[k0 * Cc + n], h0, l0);
  split_tf32(W[(k0 + 4) * Cc + n], h1, l1);
  g_Wfrag[i] = make_float4(__uint_as_float(h0), __uint_as_float(h1),
                           __uint_as_float(l0), __uint_as_float(l1));
}

// Warp grid: mtp = warp>>3 (rows mtp*32..+31), wg = warp&7 (cols wg*24..+23).
__device__ __forceinline__ void gemm_core(const float* __restrict__ sXW,
                                          const u32* __restrict__ sLo,
                                          const float4* __restrict__ wf,
                                          float acc[2][3][4], int tid) {
  const int warp = tid >> 5, lane = tid & 31;
  const int g = lane >> 2, tig = lane & 3;
  const int mtp = warp >> 3, wg = warp & 7;
#pragma unroll
  for (int mi = 0; mi < 2; mi++)
#pragma unroll
    for (int j = 0; j < 3; j++)
#pragma unroll
      for (int q = 0; q < 4; q++) acc[mi][j][q] = 0.0f;

  const float4* wfb = wf + (wg * 3) * (KCH * 32) + lane;
  // 2-deep prefetch ring: slots for kc (even/odd); 6 LDGs in flight.
  float4 bf[2][3];
#pragma unroll
  for (int j = 0; j < 3; j++) bf[0][j] = wfb[j * (KCH * 32)];
#pragma unroll
  for (int j = 0; j < 3; j++) bf[1][j] = wfb[j * (KCH * 32) + 32];

  const int r0 = mtp * 32 + g;
  const float* hp = sXW + r0 * STR + tig;
  const u32* lp = sLo + r0 * LOSTR + tig;
#pragma unroll 2
  for (int kc = 0; kc < KCH; kc++) {
    const int slot = kc & 1;
    // consume current slot, then immediately refill with kc+2 (max lead time)
    float4 cur[3];
#pragma unroll
    for (int j = 0; j < 3; j++) cur[j] = bf[slot][j];
    int kn = (kc + 2 < KCH) ? kc + 2 : 0;  // harmless wrap prefetch
#pragma unroll
    for (int j = 0; j < 3; j++) bf[slot][j] = wfb[j * (KCH * 32) + kn * 32];

    unsigned ah[2][4], al[2][4];
#pragma unroll
    for (int mi = 0; mi < 2; mi++) {
      const float* hm = hp + (mi * 16) * STR + kc * 8;
      ah[mi][0] = __float_as_uint(hm[0]);
      ah[mi][1] = __float_as_uint(hm[8 * STR]);
      ah[mi][2] = __float_as_uint(hm[4]);
      ah[mi][3] = __float_as_uint(hm[8 * STR + 4]);
      u32 p0 = lp[(mi * 16) * LOSTR + kc * 4];
      u32 p1 = lp[(mi * 16 + 8) * LOSTR + kc * 4];
      al[mi][0] = p0 << 16;           // bf16(lo[k0]) -> fp32/tf32 bits
      al[mi][2] = p0 & 0xFFFF0000u;   // bf16(lo[k0+4])
      al[mi][1] = p1 << 16;
      al[mi][3] = p1 & 0xFFFF0000u;
    }
#pragma unroll
    for (int j = 0; j < 3; j++) {
      unsigned bh0 = __float_as_uint(cur[j].x);
      unsigned bh1 = __float_as_uint(cur[j].y);
      unsigned bl0 = __float_as_uint(cur[j].z);
      unsigned bl1 = __float_as_uint(cur[j].w);
#pragma unroll
      for (int mi = 0; mi < 2; mi++) {
        mma_tf32(acc[mi][j], ah[mi][0], ah[mi][1], ah[mi][2], ah[mi][3], bh0, bh1);
        mma_tf32(acc[mi][j], ah[mi][0], ah[mi][1], ah[mi][2], ah[mi][3], bl0, bl1);
        mma_tf32(acc[mi][j], al[mi][0], al[mi][1], al[mi][2], al[mi][3], bh0, bh1);
      }
    }
  }
}

__device__ __forceinline__ void gemm_to_smem(const float* __restrict__ sXW,
                                             const u32* __restrict__ sLo,
                                             const float4* __restrict__ wf,
                                             const float* __restrict__ bias,
                                             float* __restrict__ dst, int tid) {
  float acc[2][3][4];
  gemm_core(sXW, sLo, wf, acc, tid);
  const int warp = tid >> 5, lane = tid & 31;
  const int g = lane >> 2, tig = lane & 3;
  const int mtp = warp >> 3, wg = warp & 7;
#pragma unroll
  for (int mi = 0; mi < 2; mi++) {
    const int r0 = mtp * 32 + mi * 16 + g;
#pragma unroll
    for (int j = 0; j < 3; j++) {
      const int c = wg * 24 + 8 * j + 2 * tig;
      float2 bj = *(const float2*)(bias + c);
      *(float2*)(dst + r0 * STR + c) =
          make_float2(acc[mi][j][0] + bj.x, acc[mi][j][1] + bj.y);
      *(float2*)(dst + (r0 + 8) * STR + c) =
          make_float2(acc[mi][j][2] + bj.x, acc[mi][j][3] + bj.y);
    }
  }
}

__device__ __forceinline__ void gemm_skip_out(const float* __restrict__ sXW,
                                              const u32* __restrict__ sLo,
                                              const float4* __restrict__ wf,
                                              const float* __restrict__ bias,
                                              const float* __restrict__ sAttn,
                                              float* __restrict__ out,
                                              int b, int h0, int w0, int tid) {
  float acc[2][3][4];
  gemm_core(sXW, sLo, wf, acc, tid);
  const int warp = tid >> 5, lane = tid & 31;
  const int g = lane >> 2, tig = lane & 3;
  const int mtp = warp >> 3, wg = warp & 7;
#pragma unroll
  for (int mi = 0; mi < 2; mi++) {
    const int r0 = mtp * 32 + mi * 16 + g;   // node (nh0, nw=g)
    const int r1 = r0 + 8;                   // node (nh0+1, nw=g)
    const int nh0 = mtp * 4 + mi * 2;
    const long hw0 = (long)(h0 + nh0) * Wc + w0 + g;
    const long hw1 = hw0 + Wc;
#pragma unroll
    for (int j = 0; j < 3; j++) {
      const int c = wg * 24 + 8 * j + 2 * tig;
      float2 bj = *(const float2*)(bias + c);
      float v00 = acc[mi][j][0] + bj.x + sAttn[r0 * STR + c];
      float v01 = acc[mi][j][1] + bj.y + sAttn[r0 * STR + c + 1];
      float v10 = acc[mi][j][2] + bj.x + sAttn[r1 * STR + c];
      float v11 = acc[mi][j][3] + bj.y + sAttn[r1 * STR + c + 1];
      float* base0 = out + (long)(b * Cc + c) * Hc * Wc;
      float* base1 = out + (long)(b * Cc + c + 1) * Hc * Wc;
      base0[hw0] = v00; base1[hw0] = v01;
      base0[hw1] = v10; base1[hw1] = v11;
    }
  }
}

__global__ void __launch_bounds__(NT, 1)
wg_kernel(const float* __restrict__ x,
          const float* __restrict__ bq, const float* __restrict__ bk,
          const float* __restrict__ bv, const float* __restrict__ bsk,
          float* __restrict__ out) {
  extern __shared__ float sm[];
  float* sXW = sm;               // exact xw, later tf32-hi in place
  float* sQ = sXW + XW_FLOATS;
  float* sK = sQ + XW_FLOATS;
  float* sV = sK + XW_FLOATS;
  u32* sLo = (u32*)(sV + XW_FLOATS);  // 6400 u32; first 4096 alias Gram
  float* sG = (float*)sLo;            // Gram (dead after KNN)
  float* sSq = (float*)(sLo + LO_U32);   // 64 floats
  int* sIdx = (int*)(sSq + NN);          // 64*9 ints

  const int tid = threadIdx.x;
  const int w = blockIdx.x;
  const int b = w / (NWH * NWW);
  const int rem = w - b * (NWH * NWW);
  const int wh = rem / NWW, ww = rem - wh * NWW;
  const int h0 = wh * WS, w0 = ww * WS;

  // ---- Phase A: gather window nodes ----
#pragma unroll
  for (int i = 0; i < 3; i++) {
    int t = tid + NT * i;          // 0..1535 : (c, nh)
    int c = t >> 3, nh = t & 7;
    const float* src = x + ((b * Cc + c) * Hc + h0 + nh) * Wc + w0;
    float4 v0 = *(const float4*)src;
    float4 v1 = *(const float4*)(src + 4);
    float* d = sXW + (nh * 8) * STR + c;
    d[0 * STR] = v0.x; d[1 * STR] = v0.y; d[2 * STR] = v0.z; d[3 * STR] = v0.w;
    d[4 * STR] = v1.x; d[5 * STR] = v1.y; d[6 * STR] = v1.z; d[7 * STR] = v1.w;
  }
  __syncthreads();

  // ---- Phase B1: Gram matrix (exact fp32), 1 row x 8 cols per thread ----
  {
    const int tn = tid >> 3;        // 0..63 (row)
    const int tm8 = tid & 7;        // cols tm8 + 8j
    u64 acc2[8];
#pragma unroll
    for (int j = 0; j < 8; j++) acc2[j] = 0ull;
    const float* ar = sXW + tn * STR;
#pragma unroll 2
    for (int k = 0; k < Cc; k += 4) {
      float4 a = *(const float4*)(ar + k);
      u64 alo = pack2f(a.x, a.y), ahi = pack2f(a.z, a.w);
#pragma unroll
      for (int j = 0; j < 8; j++) {
        float4 bb = *(const float4*)(sXW + (tm8 + 8 * j) * STR + k);
        fma2(acc2[j], alo, pack2f(bb.x, bb.y));
        fma2(acc2[j], ahi, pack2f(bb.z, bb.w));
      }
    }
#pragma unroll
    for (int j = 0; j < 8; j++)
      sG[tn * NN + tm8 + 8 * j] = hsum2(acc2[j]);
  }
  __syncthreads();
  if (tid < NN) sSq[tid] = sG[tid * (NN + 1)];
  __syncthreads();

  // ---- Phase B2: top-9 nearest neighbors (stable, exact fp32) ----
  if (tid < NN) {
    const int n = tid;
    unsigned long long mask = 1ull << n;  // exclude self
    const float sqn = sSq[n];
    const float* grow = sG + n * NN;
#pragma unroll 1
    for (int kk = 0; kk < KK; kk++) {
      float best = 3.0e38f;
      int bi = 0;
#pragma unroll 4
      for (int m = 0; m < NN; m++) {
        float d = sqn + sSq[m] - 2.0f * grow[m];
        if ((mask >> m) & 1ull) d = 3.9e38f;
        if (d < best) { best = d; bi = m; }  // '<' = lowest index wins ties
      }
      mask |= 1ull << bi;
      sIdx[n * KK + kk] = bi;
    }
  }
  __syncthreads();  // KNN done reading sG before sLo overwrites it

  // ---- Phase B3: split xw in place -> tf32 hi (sXW) + bf16 lo pairs ----
#pragma unroll
  for (int i = 0; i < 12; i++) {
    int p = tid + NT * i;           // 0..6143
    int row = p / 96, pr = p - row * 96;
    int kc = pr >> 2, tg = pr & 3;
    int k0 = kc * 8 + tg;
    float* xr = sXW + row * STR;
    float f0 = xr[k0], f1 = xr[k0 + 4];
    unsigned h0 = cvt_tf32(f0);
    unsigned h1 = cvt_tf32(f1);
    float l0 = f0 - __uint_as_float(h0);
    float l1 = f1 - __uint_as_float(h1);
    xr[k0] = __uint_as_float(h0);
    xr[k0 + 4] = __uint_as_float(h1);
    u32 b0 = (u32)__bfloat16_as_ushort(__float2bfloat16_rn(l0));
    u32 b1 = (u32)__bfloat16_as_ushort(__float2bfloat16_rn(l1));
    sLo[row * LOSTR + kc * 4 + tg] = b0 | (b1 << 16);
  }
  __syncthreads();

  // ---- Phase C: Q, K, V projections (tensor core, barrier-free) ----
  gemm_to_smem(sXW, sLo, g_Wfrag + 0 * FRAG_PER_MAT, bq, sQ, tid);
  gemm_to_smem(sXW, sLo, g_Wfrag + 1 * FRAG_PER_MAT, bk, sK, tid);
  gemm_to_smem(sXW, sLo, g_Wfrag + 2 * FRAG_PER_MAT, bv, sV, tid);
  __syncthreads();  // sQ/sK/sV visible before attention

  // ---- Phase D: 9-neighbor softmax attention; 512 thr = one (n,h) each ----
  {
    const int n = tid & (NN - 1);
    const int h = tid >> 6;
    const float* qp = sQ + n * STR + h * DH;
    float q[DH];
#pragma unroll
    for (int d4 = 0; d4 < DH / 4; d4++) {
      float4 v = *(const float4*)(qp + d4 * 4);
      q[d4 * 4 + 0] = v.x; q[d4 * 4 + 1] = v.y;
      q[d4 * 4 + 2] = v.z; q[d4 * 4 + 3] = v.w;
    }
    float sc[KK];
    int nb[KK];
#pragma unroll
    for (int kk = 0; kk < KK; kk++) {
      int m = sIdx[n * KK + kk];
      nb[kk] = m;
      const float* kp = sK + m * STR + h * DH;
      float s = 0.0f;
#pragma unroll
      for (int d4 = 0; d4 < DH / 4; d4++) {
        float4 v = *(const float4*)(kp + d4 * 4);
        s = fmaf(q[d4 * 4 + 0], v.x, s);
        s = fmaf(q[d4 * 4 + 1], v.y, s);
        s = fmaf(q[d4 * 4 + 2], v.z, s);
        s = fmaf(q[d4 * 4 + 3], v.w, s);
      }
      sc[kk] = s * INV_SQRT_DH;
    }
    float mx = sc[0];
#pragma unroll
    for (int kk = 1; kk < KK; kk++) mx = fmaxf(mx, sc[kk]);
    float ssum = 0.0f;
#pragma unroll
    for (int kk = 0; kk < KK; kk++) { sc[kk] = __expf(sc[kk] - mx); ssum += sc[kk]; }
    const float inv = 1.0f / ssum;
    float o[DH] = {};
#pragma unroll
    for (int kk = 0; kk < KK; kk++) {
      float a = sc[kk] * inv;
      const float* vp = sV + nb[kk] * STR + h * DH;
#pragma unroll
      for (int d4 = 0; d4 < DH / 4; d4++) {
        float4 v = *(const float4*)(vp + d4 * 4);
        o[d4 * 4 + 0] = fmaf(a, v.x, o[d4 * 4 + 0]);
        o[d4 * 4 + 1] = fmaf(a, v.y, o[d4 * 4 + 1]);
        o[d4 * 4 + 2] = fmaf(a, v.z, o[d4 * 4 + 2]);
        o[d4 * 4 + 3] = fmaf(a, v.w, o[d4 * 4 + 3]);
      }
    }
    float* op = sQ + n * STR + h * DH;  // attn out overwrites own q segment
#pragma unroll
    for (int d4 = 0; d4 < DH / 4; d4++)
      *(float4*)(op + d4 * 4) =
          make_float4(o[d4 * 4 + 0], o[d4 * 4 + 1], o[d4 * 4 + 2], o[d4 * 4 + 3]);
  }
  __syncthreads();  // attn results in sQ visible before skip epilogue reads

  // ---- Phase E: skip GEMM + attn add + scatter to [B,C,H,W] ----
  gemm_skip_out(sXW, sLo, g_Wfrag + 3 * FRAG_PER_MAT, bsk, sQ, out,
                b, h0, w0, tid);
}

extern "C" void kernel_launch(void* const* d_in, const int* in_sizes, int n_in,
                              void* d_out, int out_size) {
  const float* x   = (const float*)d_in[0];
  const float* Wq  = (const float*)d_in[1];
  const float* bq  = (const float*)d_in[2];
  const float* Wk  = (const float*)d_in[3];
  const float* bk  = (const float*)d_in[4];
  const float* Wv  = (const float*)d_in[5];
  const float* bv  = (const float*)d_in[6];
  const float* Wsk = (const float*)d_in[7];
  const float* bsk = (const float*)d_in[8];
  float* out = (float*)d_out;

  pack_w_kernel<<<(4 * FRAG_PER_MAT + 255) / 256, 256>>>(Wq, Wk, Wv, Wsk);

  cudaFuncSetAttribute(wg_kernel, cudaFuncAttributeMaxDynamicSharedMemorySize,
                       (int)SMEM_BYTES);
  wg_kernel<<<WB, NT, SMEM_BYTES>>>(x, bq, bk, bv, bsk, out);
}

// round 13
// speedup vs baseline: 1.0207x; 1.0207x over previous
#include <cuda_runtime.h>
#include <cuda_bf16.h>

// ---------------------------------------------------------------------------
// WindowGrapherPyg fused kernel, R12 = R8 warp layout (4 m-tiles x 4 col-
// groups: 6 independent B-fragment LDG streams, best measured MLP) + R10's
// one-shot A pre-split (tf32-hi in place, bf16 lo pairs in dead Gram buffer;
// zero cvt in GEMM hot loop).
// Barrier-free tensor-core GEMMs; W pre-split/pre-packed per-lane in global.
// m16n8k8 fragment map (lane = 4*g+tig):
//   A: a0=(g,k=tig) a1=(g+8,tig) a2=(g,tig+4) a3=(g+8,tig+4)
//   B: b0=(k=tig,n=g) b1=(k=tig+4,n=g)
//   D: c0=(g,2tig) c1=(g,2tig+1) c2=(g+8,2tig) c3=(g+8,2tig+1)
// ---------------------------------------------------------------------------

typedef unsigned long long u64;
typedef unsigned int u32;

namespace {
constexpr int Bc = 2, Cc = 192, Hc = 192, Wc = 192;
constexpr int WS = 8, NN = 64, KK = 9, HEADS = 8, DH = 24;
constexpr int NWH = Hc / WS, NWW = Wc / WS;         // 24 x 24
constexpr int WB = Bc * NWH * NWW;                  // 1152 windows
constexpr int STR = 196;                            // xw/Q/K/V row stride
constexpr int NT = 512;
constexpr int XW_FLOATS = NN * STR;                 // 12544
constexpr int NTILES = Cc / 8;                      // 24 n-tiles
constexpr int KCH = Cc / 8;                         // 24 k-chunks
constexpr int FRAG_PER_MAT = NTILES * KCH * 32;     // 18432 float4
constexpr int LOSTR = 100;                          // lo-pair row stride (u32)
constexpr int LO_U32 = NN * LOSTR;                  // 6400 (>= 4096 Gram alias)
constexpr size_t SMEM_BYTES =
    (size_t)(4 * XW_FLOATS + LO_U32 + NN) * sizeof(float) +
    (size_t)(NN * KK) * sizeof(int);                // 228,864 B
constexpr float INV_SQRT_DH = 0.20412414523193154f;
}

// Pre-packed tf32 hi/lo B fragments: [mat][ntile][kchunk][lane] float4.
__device__ float4 g_Wfrag[4 * FRAG_PER_MAT];

__device__ __forceinline__ u64 pack2f(float x, float y) {
  u64 r; asm("mov.b64 %0, {%1, %2};" : "=l"(r) : "f"(x), "f"(y)); return r;
}
__device__ __forceinline__ void fma2(u64& d, u64 a, u64 b) {
  asm("fma.rn.f32x2 %0, %1, %2, %0;" : "+l"(d) : "l"(a), "l"(b));
}
__device__ __forceinline__ float hsum2(u64 v) {
  float2 o; asm("mov.b64 {%0, %1}, %2;" : "=f"(o.x), "=f"(o.y) : "l"(v));
  return o.x + o.y;
}
__device__ __forceinline__ unsigned cvt_tf32(float f) {
  unsigned r; asm("cvt.rna.tf32.f32 %0, %1;" : "=r"(r) : "f"(f)); return r;
}
__device__ __forceinline__ void split_tf32(float f, unsigned& hi, unsigned& lo) {
  hi = cvt_tf32(f);
  lo = cvt_tf32(f - __uint_as_float(hi));
}
__device__ __forceinline__ void mma_tf32(float d[4], unsigned a0, unsigned a1,
                                         unsigned a2, unsigned a3,
                                         unsigned b0, unsigned b1) {
  asm("mma.sync.aligned.m16n8k8.row.col.f32.tf32.tf32.f32 "
      "{%0,%1,%2,%3}, {%4,%5,%6,%7}, {%8,%9}, {%0,%1,%2,%3};"
      : "+f"(d[0]), "+f"(d[1]), "+f"(d[2]), "+f"(d[3])
      : "r"(a0), "r"(a1), "r"(a2), "r"(a3), "r"(b0), "r"(b1));
}

// Prologue: pack W[k][n] into per-lane fragment float4s (see R8).
__global__ void pack_w_kernel(const float* __restrict__ w0,
                              const float* __restrict__ w1,
                              const float* __restrict__ w2,
                              const float* __restrict__ w3) {
  int i = blockIdx.x * blockDim.x + threadIdx.x;
  if (i >= 4 * FRAG_PER_MAT) return;
  int lane = i & 31;
  int t = i >> 5;
  int kc = t % KCH; t /= KCH;
  int ntile = t % NTILES;
  int mat = t / NTILES;
  const float* W = (mat == 0) ? w0 : (mat == 1) ? w1 : (mat == 2) ? w2 : w3;
  int n = ntile * 8 + (lane >> 2);
  int k0 = kc * 8 + (lane & 3);
  unsigned h0, l0, h1, l1;
  split_tf32(W[k0 * Cc + n], h0, l0);
  split_tf32(W[(k0 + 4) * Cc + n], h1, l1);
  g_Wfrag[i] = make_float4(__uint_as_float(h0), __uint_as_float(h1),
                           __uint_as_float(l0), __uint_as_float(l1));
}

// Warp grid (R8): mt = warp>>2 (16 rows), wg = warp&3 (48 cols = 6 n-tiles).
// A: hi from sXW (pre-split in place), lo from bf16 pair buffer.
__device__ __forceinline__ void gemm_core(const float* __restrict__ sXW,
                                          const u32* __restrict__ sLo,
                                          const float4* __restrict__ wf,
                                          float acc[6][4], int tid) {
  const int warp = tid >> 5, lane = tid & 31;
  const int g = lane >> 2, tig = lane & 3;
  const int mt = warp >> 2, wg = warp & 3;
  const int r0 = mt * 16 + g;
#pragma unroll
  for (int j = 0; j < 6; j++)
#pragma unroll
    for (int q = 0; q < 4; q++) acc[j][q] = 0.0f;

  const float4* wfb = wf + (wg * 6) * (KCH * 32) + lane;
  float4 bf[6];
#pragma unroll
  for (int j = 0; j < 6; j++) bf[j] = wfb[j * (KCH * 32)];

  const float* hp = sXW + r0 * STR + tig;
  const u32* lp = sLo + r0 * LOSTR + tig;
#pragma unroll 2
  for (int kc = 0; kc < KCH; kc++) {
    // A fragments: hi = plain LDS of valid-tf32 fp32 bits; lo = bf16 pairs.
    const float* hm = hp + kc * 8;
    unsigned ah[4], al[4];
    ah[0] = __float_as_uint(hm[0]);
    ah[1] = __float_as_uint(hm[8 * STR]);
    ah[2] = __float_as_uint(hm[4]);
    ah[3] = __float_as_uint(hm[8 * STR + 4]);
    u32 p0 = lp[kc * 4];
    u32 p1 = lp[8 * LOSTR + kc * 4];
    al[0] = p0 << 16;           // bf16(lo[k0]) -> fp32/tf32 bits
    al[2] = p0 & 0xFFFF0000u;   // bf16(lo[k0+4])
    al[1] = p1 << 16;
    al[3] = p1 & 0xFFFF0000u;

    float4 cur[6];
#pragma unroll
    for (int j = 0; j < 6; j++) cur[j] = bf[j];
    int kn = (kc + 1 < KCH) ? kc + 1 : 0;  // harmless wrap prefetch
#pragma unroll
    for (int j = 0; j < 6; j++) bf[j] = wfb[j * (KCH * 32) + kn * 32];
#pragma unroll
    for (int j = 0; j < 6; j++) {
      unsigned bh0 = __float_as_uint(cur[j].x);
      unsigned bh1 = __float_as_uint(cur[j].y);
      unsigned bl0 = __float_as_uint(cur[j].z);
      unsigned bl1 = __float_as_uint(cur[j].w);
      mma_tf32(acc[j], ah[0], ah[1], ah[2], ah[3], bh0, bh1);
      mma_tf32(acc[j], ah[0], ah[1], ah[2], ah[3], bl0, bl1);
      mma_tf32(acc[j], al[0], al[1], al[2], al[3], bh0, bh1);
    }
  }
}

__device__ __forceinline__ void gemm_to_smem(const float* __restrict__ sXW,
                                             const u32* __restrict__ sLo,
                                             const float4* __restrict__ wf,
                                             const float* __restrict__ bias,
                                             float* __restrict__ dst, int tid) {
  float acc[6][4];
  gemm_core(sXW, sLo, wf, acc, tid);
  const int warp = tid >> 5, lane = tid & 31;
  const int g = lane >> 2, tig = lane & 3;
  const int mt = warp >> 2, wg = warp & 3;
  const int r0 = mt * 16 + g;
#pragma unroll
  for (int j = 0; j < 6; j++) {
    const int c = wg * 48 + 8 * j + 2 * tig;
    float2 bj = *(const float2*)(bias + c);
    *(float2*)(dst + r0 * STR + c) =
        make_float2(acc[j][0] + bj.x, acc[j][1] + bj.y);
    *(float2*)(dst + (r0 + 8) * STR + c) =
        make_float2(acc[j][2] + bj.x, acc[j][3] + bj.y);
  }
}

__device__ __forceinline__ void gemm_skip_out(const float* __restrict__ sXW,
                                              const u32* __restrict__ sLo,
                                              const float4* __restrict__ wf,
                                              const float* __restrict__ bias,
                                              const float* __restrict__ sAttn,
                                              float* __restrict__ out,
                                              int b, int h0, int w0, int tid) {
  float acc[6][4];
  gemm_core(sXW, sLo, wf, acc, tid);
  const int warp = tid >> 5, lane = tid & 31;
  const int g = lane >> 2, tig = lane & 3;
  const int mt = warp >> 2, wg = warp & 3;
  const int r0 = mt * 16 + g;       // node (nh=2mt,   nw=g)
  const int r1 = r0 + 8;            // node (nh=2mt+1, nw=g)
  const long hw0 = (long)(h0 + 2 * mt) * Wc + w0 + g;
  const long hw1 = hw0 + Wc;
#pragma unroll
  for (int j = 0; j < 6; j++) {
    const int c = wg * 48 + 8 * j + 2 * tig;
    float2 bj = *(const float2*)(bias + c);
    float v00 = acc[j][0] + bj.x + sAttn[r0 * STR + c];
    float v01 = acc[j][1] + bj.y + sAttn[r0 * STR + c + 1];
    float v10 = acc[j][2] + bj.x + sAttn[r1 * STR + c];
    float v11 = acc[j][3] + bj.y + sAttn[r1 * STR + c + 1];
    float* base0 = out + (long)(b * Cc + c) * Hc * Wc;
    float* base1 = out + (long)(b * Cc + c + 1) * Hc * Wc;
    base0[hw0] = v00; base1[hw0] = v01;
    base0[hw1] = v10; base1[hw1] = v11;
  }
}

__global__ void __launch_bounds__(NT, 1)
wg_kernel(const float* __restrict__ x,
          const float* __restrict__ bq, const float* __restrict__ bk,
          const float* __restrict__ bv, const float* __restrict__ bsk,
          float* __restrict__ out) {
  extern __shared__ float sm[];
  float* sXW = sm;               // exact xw, later tf32-hi in place
  float* sQ = sXW + XW_FLOATS;
  float* sK = sQ + XW_FLOATS;
  float* sV = sK + XW_FLOATS;
  u32* sLo = (u32*)(sV + XW_FLOATS);  // 6400 u32; first 4096 alias Gram
  float* sG = (float*)sLo;            // Gram (dead after KNN)
  float* sSq = (float*)(sLo + LO_U32);   // 64 floats
  int* sIdx = (int*)(sSq + NN);          // 64*9 ints

  const int tid = threadIdx.x;
  const int w = blockIdx.x;
  const int b = w / (NWH * NWW);
  const int rem = w - b * (NWH * NWW);
  const int wh = rem / NWW, ww = rem - wh * NWW;
  const int h0 = wh * WS, w0 = ww * WS;

  // ---- Phase A: gather window nodes ----
#pragma unroll
  for (int i = 0; i < 3; i++) {
    int t = tid + NT * i;          // 0..1535 : (c, nh)
    int c = t >> 3, nh = t & 7;
    const float* src = x + ((b * Cc + c) * Hc + h0 + nh) * Wc + w0;
    float4 v0 = *(const float4*)src;
    float4 v1 = *(const float4*)(src + 4);
    float* d = sXW + (nh * 8) * STR + c;
    d[0 * STR] = v0.x; d[1 * STR] = v0.y; d[2 * STR] = v0.z; d[3 * STR] = v0.w;
    d[4 * STR] = v1.x; d[5 * STR] = v1.y; d[6 * STR] = v1.z; d[7 * STR] = v1.w;
  }
  __syncthreads();

  // ---- Phase B1: Gram matrix (exact fp32), 1 row x 8 cols per thread ----
  {
    const int tn = tid >> 3;        // 0..63 (row)
    const int tm8 = tid & 7;        // cols tm8 + 8j
    u64 acc2[8];
#pragma unroll
    for (int j = 0; j < 8; j++) acc2[j] = 0ull;
    const float* ar = sXW + tn * STR;
#pragma unroll 2
    for (int k = 0; k < Cc; k += 4) {
      float4 a = *(const float4*)(ar + k);
      u64 alo = pack2f(a.x, a.y), ahi = pack2f(a.z, a.w);
#pragma unroll
      for (int j = 0; j < 8; j++) {
        float4 bb = *(const float4*)(sXW + (tm8 + 8 * j) * STR + k);
        fma2(acc2[j], alo, pack2f(bb.x, bb.y));
        fma2(acc2[j], ahi, pack2f(bb.z, bb.w));
      }
    }
#pragma unroll
    for (int j = 0; j < 8; j++)
      sG[tn * NN + tm8 + 8 * j] = hsum2(acc2[j]);
  }
  __syncthreads();
  if (tid < NN) sSq[tid] = sG[tid * (NN + 1)];
  __syncthreads();

  // ---- Phase B2: top-9 nearest neighbors (stable, exact fp32) ----
  if (tid < NN) {
    const int n = tid;
    unsigned long long mask = 1ull << n;  // exclude self
    const float sqn = sSq[n];
    const float* grow = sG + n * NN;
#pragma unroll 1
    for (int kk = 0; kk < KK; kk++) {
      float best = 3.0e38f;
      int bi = 0;
#pragma unroll 4
      for (int m = 0; m < NN; m++) {
        float d = sqn + sSq[m] - 2.0f * grow[m];
        if ((mask >> m) & 1ull) d = 3.9e38f;
        if (d < best) { best = d; bi = m; }  // '<' = lowest index wins ties
      }
      mask |= 1ull << bi;
      sIdx[n * KK + kk] = bi;
    }
  }
  __syncthreads();  // KNN done reading sG before sLo overwrites it

  // ---- Phase B3: split xw in place -> tf32 hi (sXW) + bf16 lo pairs ----
#pragma unroll
  for (int i = 0; i < 12; i++) {
    int p = tid + NT * i;           // 0..6143
    int row = p / 96, pr = p - row * 96;
    int kc = pr >> 2, tg = pr & 3;
    int k0 = kc * 8 + tg;
    float* xr = sXW + row * STR;
    float f0 = xr[k0], f1 = xr[k0 + 4];
    unsigned h0 = cvt_tf32(f0);
    unsigned h1 = cvt_tf32(f1);
    float l0 = f0 - __uint_as_float(h0);
    float l1 = f1 - __uint_as_float(h1);
    xr[k0] = __uint_as_float(h0);
    xr[k0 + 4] = __uint_as_float(h1);
    u32 b0 = (u32)__bfloat16_as_ushort(__float2bfloat16_rn(l0));
    u32 b1 = (u32)__bfloat16_as_ushort(__float2bfloat16_rn(l1));
    sLo[row * LOSTR + kc * 4 + tg] = b0 | (b1 << 16);
  }
  __syncthreads();

  // ---- Phase C: Q, K, V projections (tensor core, barrier-free) ----
  gemm_to_smem(sXW, sLo, g_Wfrag + 0 * FRAG_PER_MAT, bq, sQ, tid);
  gemm_to_smem(sXW, sLo, g_Wfrag + 1 * FRAG_PER_MAT, bk, sK, tid);
  gemm_to_smem(sXW, sLo, g_Wfrag + 2 * FRAG_PER_MAT, bv, sV, tid);
  __syncthreads();  // sQ/sK/sV visible before attention

  // ---- Phase D: 9-neighbor softmax attention; 512 thr = one (n,h) each ----
  {
    const int n = tid & (NN - 1);
    const int h = tid >> 6;
    const float* qp = sQ + n * STR + h * DH;
    float q[DH];
#pragma unroll
    for (int d4 = 0; d4 < DH / 4; d4++) {
      float4 v = *(const float4*)(qp + d4 * 4);
      q[d4 * 4 + 0] = v.x; q[d4 * 4 + 1] = v.y;
      q[d4 * 4 + 2] = v.z; q[d4 * 4 + 3] = v.w;
    }
    float sc[KK];
    int nb[KK];
#pragma unroll
    for (int kk = 0; kk < KK; kk++) {
      int m = sIdx[n * KK + kk];
      nb[kk] = m;
      const float* kp = sK + m * STR + h * DH;
      float s = 0.0f;
#pragma unroll
      for (int d4 = 0; d4 < DH / 4; d4++) {
        float4 v = *(const float4*)(kp + d4 * 4);
        s = fmaf(q[d4 * 4 + 0], v.x, s);
        s = fmaf(q[d4 * 4 + 1], v.y, s);
        s = fmaf(q[d4 * 4 + 2], v.z, s);
        s = fmaf(q[d4 * 4 + 3], v.w, s);
      }
      sc[kk] = s * INV_SQRT_DH;
    }
    float mx = sc[0];
#pragma unroll
    for (int kk = 1; kk < KK; kk++) mx = fmaxf(mx, sc[kk]);
    float ssum = 0.0f;
#pragma unroll
    for (int kk = 0; kk < KK; kk++) { sc[kk] = __expf(sc[kk] - mx); ssum += sc[kk]; }
    const float inv = 1.0f / ssum;
    float o[DH] = {};
#pragma unroll
    for (int kk = 0; kk < KK; kk++) {
      float a = sc[kk] * inv;
      const float* vp = sV + nb[kk] * STR + h * DH;
#pragma unroll
      for (int d4 = 0; d4 < DH / 4; d4++) {
        float4 v = *(const float4*)(vp + d4 * 4);
        o[d4 * 4 + 0] = fmaf(a, v.x, o[d4 * 4 + 0]);
        o[d4 * 4 + 1] = fmaf(a, v.y, o[d4 * 4 + 1]);
        o[d4 * 4 + 2] = fmaf(a, v.z, o[d4 * 4 + 2]);
        o[d4 * 4 + 3] = fmaf(a, v.w, o[d4 * 4 + 3]);
      }
    }
    float* op = sQ + n * STR + h * DH;  // attn out overwrites own q segment
#pragma unroll
    for (int d4 = 0; d4 < DH / 4; d4++)
      *(float4*)(op + d4 * 4) =
          make_float4(o[d4 * 4 + 0], o[d4 * 4 + 1], o[d4 * 4 + 2], o[d4 * 4 + 3]);
  }
  __syncthreads();  // attn results in sQ visible before skip epilogue reads

  // ---- Phase E: skip GEMM + attn add + scatter to [B,C,H,W] ----
  gemm_skip_out(sXW, sLo, g_Wfrag + 3 * FRAG_PER_MAT, bsk, sQ, out,
                b, h0, w0, tid);
}

extern "C" void kernel_launch(void* const* d_in, const int* in_sizes, int n_in,
                              void* d_out, int out_size) {
  const float* x   = (const float*)d_in[0];
  const float* Wq  = (const float*)d_in[1];
  const float* bq  = (const float*)d_in[2];
  const float* Wk  = (const float*)d_in[3];
  const float* bk  = (const float*)d_in[4];
  const float* Wv  = (const float*)d_in[5];
  const float* bv  = (const float*)d_in[6];
  const float* Wsk = (const float*)d_in[7];
  const float* bsk = (const float*)d_in[8];
  float* out = (float*)d_out;

  pack_w_kernel<<<(4 * FRAG_PER_MAT + 255) / 256, 256>>>(Wq, Wk, Wv, Wsk);

  cudaFuncSetAttribute(wg_kernel, cudaFuncAttributeMaxDynamicSharedMemorySize,
                       (int)SMEM_BYTES);
  wg_kernel<<<WB, NT, SMEM_BYTES>>>(x, bq, bk, bv, bsk, out);
}

// round 14
// speedup vs baseline: 1.2157x; 1.1910x over previous
#include <cuda_runtime.h>
#include <cuda_bf16.h>

// ---------------------------------------------------------------------------
// WindowGrapherPyg fused kernel, R13: 2xBF16 (3-product hi/lo compensation)
// m16n8k16 tensor-core GEMMs. Halves MMA count, B-fragment L1 traffic and
// A LDS vs the R8/R12 3xTF32 path, with identical loop structure.
//   - exact-fp32 Gram + top-9 KNN (unchanged)
//   - one-shot A split: xw -> bf16 hi pairs (in place over dead fp32 xw)
//                          + bf16 lo pairs (in sLo, aliasing dead Gram)
//   - W pre-split/pre-packed per-lane bf16 hi/lo fragments in global (L2)
//   - barrier-free GEMMs, R8's 4x4 warp grid (6 independent B LDG streams)
// m16n8k16 fragment map (lane = 4*g+tig):
//   A (.b32 = 2 bf16, k ascending in low->high halves):
//     a0=(g, k=2tig..2tig+1)  a1=(g+8, same)  a2=(g, k+8)  a3=(g+8, k+8)
//   B: b0=(k=2tig..2tig+1, n=g)  b1=(k+8, n=g)
//   D: c0=(g,2tig) c1=(g,2tig+1) c2=(g+8,2tig) c3=(g+8,2tig+1)
// ---------------------------------------------------------------------------

typedef unsigned long long u64;
typedef unsigned int u32;

namespace {
constexpr int Bc = 2, Cc = 192, Hc = 192, Wc = 192;
constexpr int WS = 8, NN = 64, KK = 9, HEADS = 8, DH = 24;
constexpr int NWH = Hc / WS, NWW = Wc / WS;         // 24 x 24
constexpr int WB = Bc * NWH * NWW;                  // 1152 windows
constexpr int STR = 196;                            // xw/Q/K/V row stride
constexpr int NT = 512;
constexpr int XW_FLOATS = NN * STR;                 // 12544
constexpr int NTILES = Cc / 8;                      // 24 n-tiles
constexpr int KCH = Cc / 16;                        // 12 k16-chunks
constexpr int FRAG_PER_MAT = NTILES * KCH * 32;     // 9216 float4
constexpr int AST = 100;                            // A hi/lo row stride (u32)
constexpr int LO_U32 = NN * AST;                    // 6400 (>= 4096 Gram alias)
constexpr size_t SMEM_BYTES =
    (size_t)(4 * XW_FLOATS + LO_U32 + NN) * sizeof(float) +
    (size_t)(NN * KK) * sizeof(int);                // 228,864 B
constexpr float INV_SQRT_DH = 0.20412414523193154f;
}

// Pre-packed bf16 hi/lo B fragments: [mat][ntile][kchunk][lane] float4
// = {bh0, bh1, bl0, bl1} as u32 bit patterns (each u32 = 2 bf16).
__device__ float4 g_Wfrag[4 * FRAG_PER_MAT];

__device__ __forceinline__ u64 pack2f(float x, float y) {
  u64 r; asm("mov.b64 %0, {%1, %2};" : "=l"(r) : "f"(x), "f"(y)); return r;
}
__device__ __forceinline__ void fma2(u64& d, u64 a, u64 b) {
  asm("fma.rn.f32x2 %0, %1, %2, %0;" : "+l"(d) : "l"(a), "l"(b));
}
__device__ __forceinline__ float hsum2(u64 v) {
  float2 o; asm("mov.b64 {%0, %1}, %2;" : "=f"(o.x), "=f"(o.y) : "l"(v));
  return o.x + o.y;
}
__device__ __forceinline__ u32 pack_bf16x2(float lo_k, float hi_k) {
  // element with smaller k in the LOW 16 bits
  u32 a = (u32)__bfloat16_as_ushort(__float2bfloat16_rn(lo_k));
  u32 b = (u32)__bfloat16_as_ushort(__float2bfloat16_rn(hi_k));
  return a | (b << 16);
}
__device__ __forceinline__ void mma_bf16(float d[4], u32 a0, u32 a1,
                                         u32 a2, u32 a3, u32 b0, u32 b1) {
  asm("mma.sync.aligned.m16n8k16.row.col.f32.bf16.bf16.f32 "
      "{%0,%1,%2,%3}, {%4,%5,%6,%7}, {%8,%9}, {%0,%1,%2,%3};"
      : "+f"(d[0]), "+f"(d[1]), "+f"(d[2]), "+f"(d[3])
      : "r"(a0), "r"(a1), "r"(a2), "r"(a3), "r"(b0), "r"(b1));
}

// Prologue: split W into bf16 hi/lo and pack per-lane k16 fragments.
__global__ void pack_w_kernel(const float* __restrict__ w0,
                              const float* __restrict__ w1,
                              const float* __restrict__ w2,
                              const float* __restrict__ w3) {
  int i = blockIdx.x * blockDim.x + threadIdx.x;
  if (i >= 4 * FRAG_PER_MAT) return;
  int lane = i & 31;
  int t = i >> 5;
  int kc = t % KCH; t /= KCH;
  int ntile = t % NTILES;
  int mat = t / NTILES;
  const float* W = (mat == 0) ? w0 : (mat == 1) ? w1 : (mat == 2) ? w2 : w3;
  int g = lane >> 2, tig = lane & 3;
  int n = ntile * 8 + g;
  int k0 = kc * 16 + 2 * tig;
  float wa = W[(k0 + 0) * Cc + n], wb = W[(k0 + 1) * Cc + n];
  float wc = W[(k0 + 8) * Cc + n], wd = W[(k0 + 9) * Cc + n];
  float ha = __bfloat162float(__float2bfloat16_rn(wa));
  float hb = __bfloat162float(__float2bfloat16_rn(wb));
  float hc = __bfloat162float(__float2bfloat16_rn(wc));
  float hd = __bfloat162float(__float2bfloat16_rn(wd));
  u32 bh0 = pack_bf16x2(wa, wb);
  u32 bh1 = pack_bf16x2(wc, wd);
  u32 bl0 = pack_bf16x2(wa - ha, wb - hb);
  u32 bl1 = pack_bf16x2(wc - hc, wd - hd);
  g_Wfrag[i] = make_float4(__uint_as_float(bh0), __uint_as_float(bh1),
                           __uint_as_float(bl0), __uint_as_float(bl1));
}

// Warp grid (R8): mt = warp>>2 (16 rows), wg = warp&3 (48 cols = 6 n-tiles).
// A hi/lo: bf16 pairs in smem at u32 stride AST (bank == lane: conflict-free).
__device__ __forceinline__ void gemm_core(const u32* __restrict__ sAhi,
                                          const u32* __restrict__ sAlo,
                                          const float4* __restrict__ wf,
                                          float acc[6][4], int tid) {
  const int warp = tid >> 5, lane = tid & 31;
  const int g = lane >> 2, tig = lane & 3;
  const int mt = warp >> 2, wg = warp & 3;
  const int r0 = mt * 16 + g;
#pragma unroll
  for (int j = 0; j < 6; j++)
#pragma unroll
    for (int q = 0; q < 4; q++) acc[j][q] = 0.0f;

  const float4* wfb = wf + (wg * 6) * (KCH * 32) + lane;
  float4 bf[6];
#pragma unroll
  for (int j = 0; j < 6; j++) bf[j] = wfb[j * (KCH * 32)];

  const u32* hp = sAhi + r0 * AST + tig;
  const u32* lp = sAlo + r0 * AST + tig;
#pragma unroll
  for (int kc = 0; kc < KCH; kc++) {
    u32 ah[4], al[4];
    ah[0] = hp[kc * 8];
    ah[1] = hp[8 * AST + kc * 8];
    ah[2] = hp[kc * 8 + 4];
    ah[3] = hp[8 * AST + kc * 8 + 4];
    al[0] = lp[kc * 8];
    al[1] = lp[8 * AST + kc * 8];
    al[2] = lp[kc * 8 + 4];
    al[3] = lp[8 * AST + kc * 8 + 4];

    float4 cur[6];
#pragma unroll
    for (int j = 0; j < 6; j++) cur[j] = bf[j];
    int kn = (kc + 1 < KCH) ? kc + 1 : 0;  // harmless wrap prefetch
#pragma unroll
    for (int j = 0; j < 6; j++) bf[j] = wfb[j * (KCH * 32) + kn * 32];
#pragma unroll
    for (int j = 0; j < 6; j++) {
      u32 bh0 = __float_as_uint(cur[j].x);
      u32 bh1 = __float_as_uint(cur[j].y);
      u32 bl0 = __float_as_uint(cur[j].z);
      u32 bl1 = __float_as_uint(cur[j].w);
      mma_bf16(acc[j], ah[0], ah[1], ah[2], ah[3], bh0, bh1);
      mma_bf16(acc[j], ah[0], ah[1], ah[2], ah[3], bl0, bl1);
      mma_bf16(acc[j], al[0], al[1], al[2], al[3], bh0, bh1);
    }
  }
}

__device__ __forceinline__ void gemm_to_smem(const u32* __restrict__ sAhi,
                                             const u32* __restrict__ sAlo,
                                             const float4* __restrict__ wf,
                                             const float* __restrict__ bias,
                                             float* __restrict__ dst, int tid) {
  float acc[6][4];
  gemm_core(sAhi, sAlo, wf, acc, tid);
  const int warp = tid >> 5, lane = tid & 31;
  const int g = lane >> 2, tig = lane & 3;
  const int mt = warp >> 2, wg = warp & 3;
  const int r0 = mt * 16 + g;
#pragma unroll
  for (int j = 0; j < 6; j++) {
    const int c = wg * 48 + 8 * j + 2 * tig;
    float2 bj = *(const float2*)(bias + c);
    *(float2*)(dst + r0 * STR + c) =
        make_float2(acc[j][0] + bj.x, acc[j][1] + bj.y);
    *(float2*)(dst + (r0 + 8) * STR + c) =
        make_float2(acc[j][2] + bj.x, acc[j][3] + bj.y);
  }
}

__device__ __forceinline__ void gemm_skip_out(const u32* __restrict__ sAhi,
                                              const u32* __restrict__ sAlo,
                                              const float4* __restrict__ wf,
                                              const float* __restrict__ bias,
                                              const float* __restrict__ sAttn,
                                              float* __restrict__ out,
                                              int b, int h0, int w0, int tid) {
  float acc[6][4];
  gemm_core(sAhi, sAlo, wf, acc, tid);
  const int warp = tid >> 5, lane = tid & 31;
  const int g = lane >> 2, tig = lane & 3;
  const int mt = warp >> 2, wg = warp & 3;
  const int r0 = mt * 16 + g;       // node (nh=2mt,   nw=g)
  const int r1 = r0 + 8;            // node (nh=2mt+1, nw=g)
  const long hw0 = (long)(h0 + 2 * mt) * Wc + w0 + g;
  const long hw1 = hw0 + Wc;
#pragma unroll
  for (int j = 0; j < 6; j++) {
    const int c = wg * 48 + 8 * j + 2 * tig;
    float2 bj = *(const float2*)(bias + c);
    float v00 = acc[j][0] + bj.x + sAttn[r0 * STR + c];
    float v01 = acc[j][1] + bj.y + sAttn[r0 * STR + c + 1];
    float v10 = acc[j][2] + bj.x + sAttn[r1 * STR + c];
    float v11 = acc[j][3] + bj.y + sAttn[r1 * STR + c + 1];
    float* base0 = out + (long)(b * Cc + c) * Hc * Wc;
    float* base1 = out + (long)(b * Cc + c + 1) * Hc * Wc;
    base0[hw0] = v00; base1[hw0] = v01;
    base0[hw1] = v10; base1[hw1] = v11;
  }
}

__global__ void __launch_bounds__(NT, 1)
wg_kernel(const float* __restrict__ x,
          const float* __restrict__ bq, const float* __restrict__ bk,
          const float* __restrict__ bv, const float* __restrict__ bsk,
          float* __restrict__ out) {
  extern __shared__ float sm[];
  float* sXW = sm;               // exact fp32 xw; bf16-hi pairs after split
  float* sQ = sXW + XW_FLOATS;
  float* sK = sQ + XW_FLOATS;
  float* sV = sK + XW_FLOATS;
  u32* sLo = (u32*)(sV + XW_FLOATS);  // 6400 u32; first 4096 alias Gram
  float* sG = (float*)sLo;            // Gram (dead after KNN)
  float* sSq = (float*)(sLo + LO_U32);   // 64 floats
  int* sIdx = (int*)(sSq + NN);          // 64*9 ints
  u32* sAhi = (u32*)sXW;                 // bf16-hi pairs, stride AST

  const int tid = threadIdx.x;
  const int w = blockIdx.x;
  const int b = w / (NWH * NWW);
  const int rem = w - b * (NWH * NWW);
  const int wh = rem / NWW, ww = rem - wh * NWW;
  const int h0 = wh * WS, w0 = ww * WS;

  // ---- Phase A: gather window nodes ----
#pragma unroll
  for (int i = 0; i < 3; i++) {
    int t = tid + NT * i;          // 0..1535 : (c, nh)
    int c = t >> 3, nh = t & 7;
    const float* src = x + ((b * Cc + c) * Hc + h0 + nh) * Wc + w0;
    float4 v0 = *(const float4*)src;
    float4 v1 = *(const float4*)(src + 4);
    float* d = sXW + (nh * 8) * STR + c;
    d[0 * STR] = v0.x; d[1 * STR] = v0.y; d[2 * STR] = v0.z; d[3 * STR] = v0.w;
    d[4 * STR] = v1.x; d[5 * STR] = v1.y; d[6 * STR] = v1.z; d[7 * STR] = v1.w;
  }
  __syncthreads();

  // ---- Phase B1: Gram matrix (exact fp32), 1 row x 8 cols per thread ----
  {
    const int tn = tid >> 3;        // 0..63 (row)
    const int tm8 = tid & 7;        // cols tm8 + 8j
    u64 acc2[8];
#pragma unroll
    for (int j = 0; j < 8; j++) acc2[j] = 0ull;
    const float* ar = sXW + tn * STR;
#pragma unroll 2
    for (int k = 0; k < Cc; k += 4) {
      float4 a = *(const float4*)(ar + k);
      u64 alo = pack2f(a.x, a.y), ahi = pack2f(a.z, a.w);
#pragma unroll
      for (int j = 0; j < 8; j++) {
        float4 bb = *(const float4*)(sXW + (tm8 + 8 * j) * STR + k);
        fma2(acc2[j], alo, pack2f(bb.x, bb.y));
        fma2(acc2[j], ahi, pack2f(bb.z, bb.w));
      }
    }
#pragma unroll
    for (int j = 0; j < 8; j++)
      sG[tn * NN + tm8 + 8 * j] = hsum2(acc2[j]);
  }
  __syncthreads();
  if (tid < NN) sSq[tid] = sG[tid * (NN + 1)];
  __syncthreads();

  // ---- Phase B2: top-9 nearest neighbors (stable, exact fp32) ----
  if (tid < NN) {
    const int n = tid;
    unsigned long long mask = 1ull << n;  // exclude self
    const float sqn = sSq[n];
    const float* grow = sG + n * NN;
#pragma unroll 1
    for (int kk = 0; kk < KK; kk++) {
      float best = 3.0e38f;
      int bi = 0;
#pragma unroll 4
      for (int m = 0; m < NN; m++) {
        float d = sqn + sSq[m] - 2.0f * grow[m];
        if ((mask >> m) & 1ull) d = 3.9e38f;
        if (d < best) { best = d; bi = m; }  // '<' = lowest index wins ties
      }
      mask |= 1ull << bi;
      sIdx[n * KK + kk] = bi;
    }
  }
  __syncthreads();  // KNN done reading sG before sLo overwrites it

  // ---- Phase B3: split xw -> bf16 hi pairs (over sXW) + bf16 lo pairs ----
  // Read everything into regs first, sync, then write (in-place over fp32).
  {
    u32 hbuf[12], lbuf[12];
#pragma unroll
    for (int i = 0; i < 12; i++) {
      int p = tid + NT * i;         // 0..6143
      int row = p / 96, idx = p - row * 96;
      const float* xr = sXW + row * STR;
      float f0 = xr[2 * idx], f1 = xr[2 * idx + 1];
      float h0 = __bfloat162float(__float2bfloat16_rn(f0));
      float h1 = __bfloat162float(__float2bfloat16_rn(f1));
      hbuf[i] = pack_bf16x2(f0, f1);
      lbuf[i] = pack_bf16x2(f0 - h0, f1 - h1);
    }
    __syncthreads();  // all fp32 reads done before overwriting
#pragma unroll
    for (int i = 0; i < 12; i++) {
      int p = tid + NT * i;
      int row = p / 96, idx = p - row * 96;
      sAhi[row * AST + idx] = hbuf[i];
      sLo[row * AST + idx] = lbuf[i];
    }
  }
  __syncthreads();

  // ---- Phase C: Q, K, V projections (bf16 tensor core, barrier-free) ----
  gemm_to_smem(sAhi, sLo, g_Wfrag + 0 * FRAG_PER_MAT, bq, sQ, tid);
  gemm_to_smem(sAhi, sLo, g_Wfrag + 1 * FRAG_PER_MAT, bk, sK, tid);
  gemm_to_smem(sAhi, sLo, g_Wfrag + 2 * FRAG_PER_MAT, bv, sV, tid);
  __syncthreads();  // sQ/sK/sV visible before attention

  // ---- Phase D: 9-neighbor softmax attention; 512 thr = one (n,h) each ----
  {
    const int n = tid & (NN - 1);
    const int h = tid >> 6;
    const float* qp = sQ + n * STR + h * DH;
    float q[DH];
#pragma unroll
    for (int d4 = 0; d4 < DH / 4; d4++) {
      float4 v = *(const float4*)(qp + d4 * 4);
      q[d4 * 4 + 0] = v.x; q[d4 * 4 + 1] = v.y;
      q[d4 * 4 + 2] = v.z; q[d4 * 4 + 3] = v.w;
    }
    float sc[KK];
    int nb[KK];
#pragma unroll
    for (int kk = 0; kk < KK; kk++) {
      int m = sIdx[n * KK + kk];
      nb[kk] = m;
      const float* kp = sK + m * STR + h * DH;
      float s = 0.0f;
#pragma unroll
      for (int d4 = 0; d4 < DH / 4; d4++) {
        float4 v = *(const float4*)(kp + d4 * 4);
        s = fmaf(q[d4 * 4 + 0], v.x, s);
        s = fmaf(q[d4 * 4 + 1], v.y, s);
        s = fmaf(q[d4 * 4 + 2], v.z, s);
        s = fmaf(q[d4 * 4 + 3], v.w, s);
      }
      sc[kk] = s * INV_SQRT_DH;
    }
    float mx = sc[0];
#pragma unroll
    for (int kk = 1; kk < KK; kk++) mx = fmaxf(mx, sc[kk]);
    float ssum = 0.0f;
#pragma unroll
    for (int kk = 0; kk < KK; kk++) { sc[kk] = __expf(sc[kk] - mx); ssum += sc[kk]; }
    const float inv = 1.0f / ssum;
    float o[DH] = {};
#pragma unroll
    for (int kk = 0; kk < KK; kk++) {
      float a = sc[kk] * inv;
      const float* vp = sV + nb[kk] * STR + h * DH;
#pragma unroll
      for (int d4 = 0; d4 < DH / 4; d4++) {
        float4 v = *(const float4*)(vp + d4 * 4);
        o[d4 * 4 + 0] = fmaf(a, v.x, o[d4 * 4 + 0]);
        o[d4 * 4 + 1] = fmaf(a, v.y, o[d4 * 4 + 1]);
        o[d4 * 4 + 2] = fmaf(a, v.z, o[d4 * 4 + 2]);
        o[d4 * 4 + 3] = fmaf(a, v.w, o[d4 * 4 + 3]);
      }
    }
    float* op = sQ + n * STR + h * DH;  // attn out overwrites own q segment
#pragma unroll
    for (int d4 = 0; d4 < DH / 4; d4++)
      *(float4*)(op + d4 * 4) =
          make_float4(o[d4 * 4 + 0], o[d4 * 4 + 1], o[d4 * 4 + 2], o[d4 * 4 + 3]);
  }
  __syncthreads();  // attn results in sQ visible before skip epilogue reads

  // ---- Phase E: skip GEMM + attn add + scatter to [B,C,H,W] ----
  gemm_skip_out(sAhi, sLo, g_Wfrag + 3 * FRAG_PER_MAT, bsk, sQ, out,
                b, h0, w0, tid);
}

extern "C" void kernel_launch(void* const* d_in, const int* in_sizes, int n_in,
                              void* d_out, int out_size) {
  const float* x   = (const float*)d_in[0];
  const float* Wq  = (const float*)d_in[1];
  const float* bq  = (const float*)d_in[2];
  const float* Wk  = (const float*)d_in[3];
  const float* bk  = (const float*)d_in[4];
  const float* Wv  = (const float*)d_in[5];
  const float* bv  = (const float*)d_in[6];
  const float* Wsk = (const float*)d_in[7];
  const float* bsk = (const float*)d_in[8];
  float* out = (float*)d_out;

  pack_w_kernel<<<(4 * FRAG_PER_MAT + 255) / 256, 256>>>(Wq, Wk, Wv, Wsk);

  cudaFuncSetAttribute(wg_kernel, cudaFuncAttributeMaxDynamicSharedMemorySize,
                       (int)SMEM_BYTES);
  wg_kernel<<<WB, NT, SMEM_BYTES>>>(x, bq, bk, bv, bsk, out);
}

// round 15
// speedup vs baseline: 1.3701x; 1.1270x over previous
#include <cuda_runtime.h>
#include <cuda_bf16.h>

// ---------------------------------------------------------------------------
// WindowGrapherPyg fused kernel, R14 = R13 + low-traffic Gram (4x4 spread
// tiles over 256 threads, conflict-free ulonglong2 loads — exact fp32 math,
// 2.25x fewer LDS wavefronts than the 1x8 version).
// GEMMs: 2xBF16 3-product (hi*hi + hi*lo + lo*hi) m16n8k16, barrier-free,
// R8 4x4 warp grid, W pre-split/packed per-lane in global, A pre-split once.
// m16n8k16 fragment map (lane = 4*g+tig):
//   A: a0=(g, k=2tig..2tig+1) a1=(g+8, same) a2=(g, k+8) a3=(g+8, k+8)
//   B: b0=(k=2tig..2tig+1, n=g) b1=(k+8, n=g)
//   D: c0=(g,2tig) c1=(g,2tig+1) c2=(g+8,2tig) c3=(g+8,2tig+1)
// ---------------------------------------------------------------------------

typedef unsigned long long u64;
typedef unsigned int u32;

namespace {
constexpr int Bc = 2, Cc = 192, Hc = 192, Wc = 192;
constexpr int WS = 8, NN = 64, KK = 9, HEADS = 8, DH = 24;
constexpr int NWH = Hc / WS, NWW = Wc / WS;         // 24 x 24
constexpr int WB = Bc * NWH * NWW;                  // 1152 windows
constexpr int STR = 196;                            // xw/Q/K/V row stride
constexpr int NT = 512;
constexpr int XW_FLOATS = NN * STR;                 // 12544
constexpr int NTILES = Cc / 8;                      // 24 n-tiles
constexpr int KCH = Cc / 16;                        // 12 k16-chunks
constexpr int FRAG_PER_MAT = NTILES * KCH * 32;     // 9216 float4
constexpr int AST = 100;                            // A hi/lo row stride (u32)
constexpr int LO_U32 = NN * AST;                    // 6400 (>= 4096 Gram alias)
constexpr size_t SMEM_BYTES =
    (size_t)(4 * XW_FLOATS + LO_U32 + NN) * sizeof(float) +
    (size_t)(NN * KK) * sizeof(int);                // 228,864 B
constexpr float INV_SQRT_DH = 0.20412414523193154f;
}

// Pre-packed bf16 hi/lo B fragments: [mat][ntile][kchunk][lane] float4
// = {bh0, bh1, bl0, bl1} as u32 bit patterns (each u32 = 2 bf16).
__device__ float4 g_Wfrag[4 * FRAG_PER_MAT];

__device__ __forceinline__ void fma2(u64& d, u64 a, u64 b) {
  asm("fma.rn.f32x2 %0, %1, %2, %0;" : "+l"(d) : "l"(a), "l"(b));
}
__device__ __forceinline__ float hsum2(u64 v) {
  float2 o; asm("mov.b64 {%0, %1}, %2;" : "=f"(o.x), "=f"(o.y) : "l"(v));
  return o.x + o.y;
}
__device__ __forceinline__ u32 pack_bf16x2(float lo_k, float hi_k) {
  // element with smaller k in the LOW 16 bits
  u32 a = (u32)__bfloat16_as_ushort(__float2bfloat16_rn(lo_k));
  u32 b = (u32)__bfloat16_as_ushort(__float2bfloat16_rn(hi_k));
  return a | (b << 16);
}
__device__ __forceinline__ void mma_bf16(float d[4], u32 a0, u32 a1,
                                         u32 a2, u32 a3, u32 b0, u32 b1) {
  asm("mma.sync.aligned.m16n8k16.row.col.f32.bf16.bf16.f32 "
      "{%0,%1,%2,%3}, {%4,%5,%6,%7}, {%8,%9}, {%0,%1,%2,%3};"
      : "+f"(d[0]), "+f"(d[1]), "+f"(d[2]), "+f"(d[3])
      : "r"(a0), "r"(a1), "r"(a2), "r"(a3), "r"(b0), "r"(b1));
}

// Prologue: split W into bf16 hi/lo and pack per-lane k16 fragments.
__global__ void pack_w_kernel(const float* __restrict__ w0,
                              const float* __restrict__ w1,
                              const float* __restrict__ w2,
                              const float* __restrict__ w3) {
  int i = blockIdx.x * blockDim.x + threadIdx.x;
  if (i >= 4 * FRAG_PER_MAT) return;
  int lane = i & 31;
  int t = i >> 5;
  int kc = t % KCH; t /= KCH;
  int ntile = t % NTILES;
  int mat = t / NTILES;
  const float* W = (mat == 0) ? w0 : (mat == 1) ? w1 : (mat == 2) ? w2 : w3;
  int g = lane >> 2, tig = lane & 3;
  int n = ntile * 8 + g;
  int k0 = kc * 16 + 2 * tig;
  float wa = W[(k0 + 0) * Cc + n], wb = W[(k0 + 1) * Cc + n];
  float wc = W[(k0 + 8) * Cc + n], wd = W[(k0 + 9) * Cc + n];
  float ha = __bfloat162float(__float2bfloat16_rn(wa));
  float hb = __bfloat162float(__float2bfloat16_rn(wb));
  float hc = __bfloat162float(__float2bfloat16_rn(wc));
  float hd = __bfloat162float(__float2bfloat16_rn(wd));
  u32 bh0 = pack_bf16x2(wa, wb);
  u32 bh1 = pack_bf16x2(wc, wd);
  u32 bl0 = pack_bf16x2(wa - ha, wb - hb);
  u32 bl1 = pack_bf16x2(wc - hc, wd - hd);
  g_Wfrag[i] = make_float4(__uint_as_float(bh0), __uint_as_float(bh1),
                           __uint_as_float(bl0), __uint_as_float(bl1));
}

// Warp grid (R8): mt = warp>>2 (16 rows), wg = warp&3 (48 cols = 6 n-tiles).
__device__ __forceinline__ void gemm_core(const u32* __restrict__ sAhi,
                                          const u32* __restrict__ sAlo,
                                          const float4* __restrict__ wf,
                                          float acc[6][4], int tid) {
  const int warp = tid >> 5, lane = tid & 31;
  const int g = lane >> 2, tig = lane & 3;
  const int mt = warp >> 2, wg = warp & 3;
  const int r0 = mt * 16 + g;
#pragma unroll
  for (int j = 0; j < 6; j++)
#pragma unroll
    for (int q = 0; q < 4; q++) acc[j][q] = 0.0f;

  const float4* wfb = wf + (wg * 6) * (KCH * 32) + lane;
  float4 bf[6];
#pragma unroll
  for (int j = 0; j < 6; j++) bf[j] = wfb[j * (KCH * 32)];

  const u32* hp = sAhi + r0 * AST + tig;
  const u32* lp = sAlo + r0 * AST + tig;
#pragma unroll
  for (int kc = 0; kc < KCH; kc++) {
    u32 ah[4], al[4];
    ah[0] = hp[kc * 8];
    ah[1] = hp[8 * AST + kc * 8];
    ah[2] = hp[kc * 8 + 4];
    ah[3] = hp[8 * AST + kc * 8 + 4];
    al[0] = lp[kc * 8];
    al[1] = lp[8 * AST + kc * 8];
    al[2] = lp[kc * 8 + 4];
    al[3] = lp[8 * AST + kc * 8 + 4];

    float4 cur[6];
#pragma unroll
    for (int j = 0; j < 6; j++) cur[j] = bf[j];
    int kn = (kc + 1 < KCH) ? kc + 1 : 0;  // harmless wrap prefetch
#pragma unroll
    for (int j = 0; j < 6; j++) bf[j] = wfb[j * (KCH * 32) + kn * 32];
#pragma unroll
    for (int j = 0; j < 6; j++) {
      u32 bh0 = __float_as_uint(cur[j].x);
      u32 bh1 = __float_as_uint(cur[j].y);
      u32 bl0 = __float_as_uint(cur[j].z);
      u32 bl1 = __float_as_uint(cur[j].w);
      mma_bf16(acc[j], ah[0], ah[1], ah[2], ah[3], bh0, bh1);
      mma_bf16(acc[j], ah[0], ah[1], ah[2], ah[3], bl0, bl1);
      mma_bf16(acc[j], al[0], al[1], al[2], al[3], bh0, bh1);
    }
  }
}

__device__ __forceinline__ void gemm_to_smem(const u32* __restrict__ sAhi,
                                             const u32* __restrict__ sAlo,
                                             const float4* __restrict__ wf,
                                             const float* __restrict__ bias,
                                             float* __restrict__ dst, int tid) {
  float acc[6][4];
  gemm_core(sAhi, sAlo, wf, acc, tid);
  const int warp = tid >> 5, lane = tid & 31;
  const int g = lane >> 2, tig = lane & 3;
  const int mt = warp >> 2, wg = warp & 3;
  const int r0 = mt * 16 + g;
#pragma unroll
  for (int j = 0; j < 6; j++) {
    const int c = wg * 48 + 8 * j + 2 * tig;
    float2 bj = *(const float2*)(bias + c);
    *(float2*)(dst + r0 * STR + c) =
        make_float2(acc[j][0] + bj.x, acc[j][1] + bj.y);
    *(float2*)(dst + (r0 + 8) * STR + c) =
        make_float2(acc[j][2] + bj.x, acc[j][3] + bj.y);
  }
}

__device__ __forceinline__ void gemm_skip_out(const u32* __restrict__ sAhi,
                                              const u32* __restrict__ sAlo,
                                              const float4* __restrict__ wf,
                                              const float* __restrict__ bias,
                                              const float* __restrict__ sAttn,
                                              float* __restrict__ out,
                                              int b, int h0, int w0, int tid) {
  float acc[6][4];
  gemm_core(sAhi, sAlo, wf, acc, tid);
  const int warp = tid >> 5, lane = tid & 31;
  const int g = lane >> 2, tig = lane & 3;
  const int mt = warp >> 2, wg = warp & 3;
  const int r0 = mt * 16 + g;       // node (nh=2mt,   nw=g)
  const int r1 = r0 + 8;            // node (nh=2mt+1, nw=g)
  const long hw0 = (long)(h0 + 2 * mt) * Wc + w0 + g;
  const long hw1 = hw0 + Wc;
#pragma unroll
  for (int j = 0; j < 6; j++) {
    const int c = wg * 48 + 8 * j + 2 * tig;
    float2 bj = *(const float2*)(bias + c);
    float v00 = acc[j][0] + bj.x + sAttn[r0 * STR + c];
    float v01 = acc[j][1] + bj.y + sAttn[r0 * STR + c + 1];
    float v10 = acc[j][2] + bj.x + sAttn[r1 * STR + c];
    float v11 = acc[j][3] + bj.y + sAttn[r1 * STR + c + 1];
    float* base0 = out + (long)(b * Cc + c) * Hc * Wc;
    float* base1 = out + (long)(b * Cc + c + 1) * Hc * Wc;
    base0[hw0] = v00; base1[hw0] = v01;
    base0[hw1] = v10; base1[hw1] = v11;
  }
}

__global__ void __launch_bounds__(NT, 1)
wg_kernel(const float* __restrict__ x,
          const float* __restrict__ bq, const float* __restrict__ bk,
          const float* __restrict__ bv, const float* __restrict__ bsk,
          float* __restrict__ out) {
  extern __shared__ float sm[];
  float* sXW = sm;               // exact fp32 xw; bf16-hi pairs after split
  float* sQ = sXW + XW_FLOATS;
  float* sK = sQ + XW_FLOATS;
  float* sV = sK + XW_FLOATS;
  u32* sLo = (u32*)(sV + XW_FLOATS);  // 6400 u32; first 4096 alias Gram
  float* sG = (float*)sLo;            // Gram (dead after KNN)
  float* sSq = (float*)(sLo + LO_U32);   // 64 floats
  int* sIdx = (int*)(sSq + NN);          // 64*9 ints
  u32* sAhi = (u32*)sXW;                 // bf16-hi pairs, stride AST

  const int tid = threadIdx.x;
  const int w = blockIdx.x;
  const int b = w / (NWH * NWW);
  const int rem = w - b * (NWH * NWW);
  const int wh = rem / NWW, ww = rem - wh * NWW;
  const int h0 = wh * WS, w0 = ww * WS;

  // ---- Phase A: gather window nodes ----
#pragma unroll
  for (int i = 0; i < 3; i++) {
    int t = tid + NT * i;          // 0..1535 : (c, nh)
    int c = t >> 3, nh = t & 7;
    const float* src = x + ((b * Cc + c) * Hc + h0 + nh) * Wc + w0;
    float4 v0 = *(const float4*)src;
    float4 v1 = *(const float4*)(src + 4);
    float* d = sXW + (nh * 8) * STR + c;
    d[0 * STR] = v0.x; d[1 * STR] = v0.y; d[2 * STR] = v0.z; d[3 * STR] = v0.w;
    d[4 * STR] = v1.x; d[5 * STR] = v1.y; d[6 * STR] = v1.z; d[7 * STR] = v1.w;
  }
  __syncthreads();

  // ---- Phase B1: Gram matrix (exact fp32), 256 thr, 4x4 spread tiles ----
  // rows {tn+16i}, cols {tm+16j}: conflict-free 16B loads (lane stride 784B).
  if (tid < 256) {
    const int tn = tid >> 4, tm = tid & 15;
    u64 acc2[4][4] = {};
#pragma unroll 2
    for (int k = 0; k < Cc; k += 4) {
      ulonglong2 a[4], bb[4];
#pragma unroll
      for (int i = 0; i < 4; i++)
        a[i] = *(const ulonglong2*)(sXW + (tn + 16 * i) * STR + k);
#pragma unroll
      for (int j = 0; j < 4; j++)
        bb[j] = *(const ulonglong2*)(sXW + (tm + 16 * j) * STR + k);
#pragma unroll
      for (int i = 0; i < 4; i++)
#pragma unroll
        for (int j = 0; j < 4; j++) {
          fma2(acc2[i][j], a[i].x, bb[j].x);
          fma2(acc2[i][j], a[i].y, bb[j].y);
        }
    }
#pragma unroll
    for (int i = 0; i < 4; i++)
#pragma unroll
      for (int j = 0; j < 4; j++)
        sG[(tn + 16 * i) * NN + tm + 16 * j] = hsum2(acc2[i][j]);
  }
  __syncthreads();
  if (tid < NN) sSq[tid] = sG[tid * (NN + 1)];
  __syncthreads();

  // ---- Phase B2: top-9 nearest neighbors (stable, exact fp32) ----
  if (tid < NN) {
    const int n = tid;
    unsigned long long mask = 1ull << n;  // exclude self
    const float sqn = sSq[n];
    const float* grow = sG + n * NN;
#pragma unroll 1
    for (int kk = 0; kk < KK; kk++) {
      float best = 3.0e38f;
      int bi = 0;
#pragma unroll 4
      for (int m = 0; m < NN; m++) {
        float d = sqn + sSq[m] - 2.0f * grow[m];
        if ((mask >> m) & 1ull) d = 3.9e38f;
        if (d < best) { best = d; bi = m; }  // '<' = lowest index wins ties
      }
      mask |= 1ull << bi;
      sIdx[n * KK + kk] = bi;
    }
  }
  __syncthreads();  // KNN done reading sG before sLo overwrites it

  // ---- Phase B3: split xw -> bf16 hi pairs (over sXW) + bf16 lo pairs ----
  {
    u32 hbuf[12], lbuf[12];
#pragma unroll
    for (int i = 0; i < 12; i++) {
      int p = tid + NT * i;         // 0..6143
      int row = p / 96, idx = p - row * 96;
      const float* xr = sXW + row * STR;
      float f0 = xr[2 * idx], f1 = xr[2 * idx + 1];
      float h0 = __bfloat162float(__float2bfloat16_rn(f0));
      float h1 = __bfloat162float(__float2bfloat16_rn(f1));
      hbuf[i] = pack_bf16x2(f0, f1);
      lbuf[i] = pack_bf16x2(f0 - h0, f1 - h1);
    }
    __syncthreads();  // all fp32 reads done before overwriting
#pragma unroll
    for (int i = 0; i < 12; i++) {
      int p = tid + NT * i;
      int row = p / 96, idx = p - row * 96;
      sAhi[row * AST + idx] = hbuf[i];
      sLo[row * AST + idx] = lbuf[i];
    }
  }
  __syncthreads();

  // ---- Phase C: Q, K, V projections (bf16 tensor core, barrier-free) ----
  gemm_to_smem(sAhi, sLo, g_Wfrag + 0 * FRAG_PER_MAT, bq, sQ, tid);
  gemm_to_smem(sAhi, sLo, g_Wfrag + 1 * FRAG_PER_MAT, bk, sK, tid);
  gemm_to_smem(sAhi, sLo, g_Wfrag + 2 * FRAG_PER_MAT, bv, sV, tid);
  __syncthreads();  // sQ/sK/sV visible before attention

  // ---- Phase D: 9-neighbor softmax attention; 512 thr = one (n,h) each ----
  {
    const int n = tid & (NN - 1);
    const int h = tid >> 6;
    const float* qp = sQ + n * STR + h * DH;
    float q[DH];
#pragma unroll
    for (int d4 = 0; d4 < DH / 4; d4++) {
      float4 v = *(const float4*)(qp + d4 * 4);
      q[d4 * 4 + 0] = v.x; q[d4 * 4 + 1] = v.y;
      q[d4 * 4 + 2] = v.z; q[d4 * 4 + 3] = v.w;
    }
    float sc[KK];
    int nb[KK];
#pragma unroll
    for (int kk = 0; kk < KK; kk++) {
      int m = sIdx[n * KK + kk];
      nb[kk] = m;
      const float* kp = sK + m * STR + h * DH;
      float s = 0.0f;
#pragma unroll
      for (int d4 = 0; d4 < DH / 4; d4++) {
        float4 v = *(const float4*)(kp + d4 * 4);
        s = fmaf(q[d4 * 4 + 0], v.x, s);
        s = fmaf(q[d4 * 4 + 1], v.y, s);
        s = fmaf(q[d4 * 4 + 2], v.z, s);
        s = fmaf(q[d4 * 4 + 3], v.w, s);
      }
      sc[kk] = s * INV_SQRT_DH;
    }
    float mx = sc[0];
#pragma unroll
    for (int kk = 1; kk < KK; kk++) mx = fmaxf(mx, sc[kk]);
    float ssum = 0.0f;
#pragma unroll
    for (int kk = 0; kk < KK; kk++) { sc[kk] = __expf(sc[kk] - mx); ssum += sc[kk]; }
    const float inv = 1.0f / ssum;
    float o[DH] = {};
#pragma unroll
    for (int kk = 0; kk < KK; kk++) {
      float a = sc[kk] * inv;
      const float* vp = sV + nb[kk] * STR + h * DH;
#pragma unroll
      for (int d4 = 0; d4 < DH / 4; d4++) {
        float4 v = *(const float4*)(vp + d4 * 4);
        o[d4 * 4 + 0] = fmaf(a, v.x, o[d4 * 4 + 0]);
        o[d4 * 4 + 1] = fmaf(a, v.y, o[d4 * 4 + 1]);
        o[d4 * 4 + 2] = fmaf(a, v.z, o[d4 * 4 + 2]);
        o[d4 * 4 + 3] = fmaf(a, v.w, o[d4 * 4 + 3]);
      }
    }
    float* op = sQ + n * STR + h * DH;  // attn out overwrites own q segment
#pragma unroll
    for (int d4 = 0; d4 < DH / 4; d4++)
      *(float4*)(op + d4 * 4) =
          make_float4(o[d4 * 4 + 0], o[d4 * 4 + 1], o[d4 * 4 + 2], o[d4 * 4 + 3]);
  }
  __syncthreads();  // attn results in sQ visible before skip epilogue reads

  // ---- Phase E: skip GEMM + attn add + scatter to [B,C,H,W] ----
  gemm_skip_out(sAhi, sLo, g_Wfrag + 3 * FRAG_PER_MAT, bsk, sQ, out,
                b, h0, w0, tid);
}

extern "C" void kernel_launch(void* const* d_in, const int* in_sizes, int n_in,
                              void* d_out, int out_size) {
  const float* x   = (const float*)d_in[0];
  const float* Wq  = (const float*)d_in[1];
  const float* bq  = (const float*)d_in[2];
  const float* Wk  = (const float*)d_in[3];
  const float* bk  = (const float*)d_in[4];
  const float* Wv  = (const float*)d_in[5];
  const float* bv  = (const float*)d_in[6];
  const float* Wsk = (const float*)d_in[7];
  const float* bsk = (const float*)d_in[8];
  float* out = (float*)d_out;

  pack_w_kernel<<<(4 * FRAG_PER_MAT + 255) / 256, 256>>>(Wq, Wk, Wv, Wsk);

  cudaFuncSetAttribute(wg_kernel, cudaFuncAttributeMaxDynamicSharedMemorySize,
                       (int)SMEM_BYTES);
  wg_kernel<<<WB, NT, SMEM_BYTES>>>(x, bq, bk, bv, bsk, out);
}

// round 16
// speedup vs baseline: 1.5742x; 1.1490x over previous
#include <cuda_runtime.h>
#include <cuda_bf16.h>

// ---------------------------------------------------------------------------
// WindowGrapherPyg fused kernel, R15 = R14 + full-width Gram (16 warps,
// 2x4 thread tiles) + parallel KNN (8 lanes/node, shfl lexicographic min
// with exact serial semantics: strict '<', lowest index wins ties).
// GEMMs: 2xBF16 3-product (hi*hi + hi*lo + lo*hi) m16n8k16, barrier-free,
// R8 4x4 warp grid, W pre-split/packed per-lane in global, A pre-split once.
// m16n8k16 fragment map (lane = 4*g+tig):
//   A: a0=(g, k=2tig..2tig+1) a1=(g+8, same) a2=(g, k+8) a3=(g+8, k+8)
//   B: b0=(k=2tig..2tig+1, n=g) b1=(k+8, n=g)
//   D: c0=(g,2tig) c1=(g,2tig+1) c2=(g+8,2tig) c3=(g+8,2tig+1)
// ---------------------------------------------------------------------------

typedef unsigned long long u64;
typedef unsigned int u32;

namespace {
constexpr int Bc = 2, Cc = 192, Hc = 192, Wc = 192;
constexpr int WS = 8, NN = 64, KK = 9, HEADS = 8, DH = 24;
constexpr int NWH = Hc / WS, NWW = Wc / WS;         // 24 x 24
constexpr int WB = Bc * NWH * NWW;                  // 1152 windows
constexpr int STR = 196;                            // xw/Q/K/V row stride
constexpr int NT = 512;
constexpr int XW_FLOATS = NN * STR;                 // 12544
constexpr int NTILES = Cc / 8;                      // 24 n-tiles
constexpr int KCH = Cc / 16;                        // 12 k16-chunks
constexpr int FRAG_PER_MAT = NTILES * KCH * 32;     // 9216 float4
constexpr int AST = 100;                            // A hi/lo row stride (u32)
constexpr int LO_U32 = NN * AST;                    // 6400 (>= 4096 Gram alias)
constexpr size_t SMEM_BYTES =
    (size_t)(4 * XW_FLOATS + LO_U32 + NN) * sizeof(float) +
    (size_t)(NN * KK) * sizeof(int);                // 228,864 B
constexpr float INV_SQRT_DH = 0.20412414523193154f;
}

// Pre-packed bf16 hi/lo B fragments: [mat][ntile][kchunk][lane] float4
// = {bh0, bh1, bl0, bl1} as u32 bit patterns (each u32 = 2 bf16).
__device__ float4 g_Wfrag[4 * FRAG_PER_MAT];

__device__ __forceinline__ void fma2(u64& d, u64 a, u64 b) {
  asm("fma.rn.f32x2 %0, %1, %2, %0;" : "+l"(d) : "l"(a), "l"(b));
}
__device__ __forceinline__ float hsum2(u64 v) {
  float2 o; asm("mov.b64 {%0, %1}, %2;" : "=f"(o.x), "=f"(o.y) : "l"(v));
  return o.x + o.y;
}
__device__ __forceinline__ u32 pack_bf16x2(float lo_k, float hi_k) {
  // element with smaller k in the LOW 16 bits
  u32 a = (u32)__bfloat16_as_ushort(__float2bfloat16_rn(lo_k));
  u32 b = (u32)__bfloat16_as_ushort(__float2bfloat16_rn(hi_k));
  return a | (b << 16);
}
// order-preserving float -> u32 (total order matching IEEE < for all finite)
__device__ __forceinline__ u32 ordf(float f) {
  u32 b = __float_as_uint(f);
  return b ^ ((b >> 31) ? 0xFFFFFFFFu : 0x80000000u);
}
__device__ __forceinline__ void mma_bf16(float d[4], u32 a0, u32 a1,
                                         u32 a2, u32 a3, u32 b0, u32 b1) {
  asm("mma.sync.aligned.m16n8k16.row.col.f32.bf16.bf16.f32 "
      "{%0,%1,%2,%3}, {%4,%5,%6,%7}, {%8,%9}, {%0,%1,%2,%3};"
      : "+f"(d[0]), "+f"(d[1]), "+f"(d[2]), "+f"(d[3])
      : "r"(a0), "r"(a1), "r"(a2), "r"(a3), "r"(b0), "r"(b1));
}

// Prologue: split W into bf16 hi/lo and pack per-lane k16 fragments.
__global__ void pack_w_kernel(const float* __restrict__ w0,
                              const float* __restrict__ w1,
                              const float* __restrict__ w2,
                              const float* __restrict__ w3) {
  int i = blockIdx.x * blockDim.x + threadIdx.x;
  if (i >= 4 * FRAG_PER_MAT) return;
  int lane = i & 31;
  int t = i >> 5;
  int kc = t % KCH; t /= KCH;
  int ntile = t % NTILES;
  int mat = t / NTILES;
  const float* W = (mat == 0) ? w0 : (mat == 1) ? w1 : (mat == 2) ? w2 : w3;
  int g = lane >> 2, tig = lane & 3;
  int n = ntile * 8 + g;
  int k0 = kc * 16 + 2 * tig;
  float wa = W[(k0 + 0) * Cc + n], wb = W[(k0 + 1) * Cc + n];
  float wc = W[(k0 + 8) * Cc + n], wd = W[(k0 + 9) * Cc + n];
  float ha = __bfloat162float(__float2bfloat16_rn(wa));
  float hb = __bfloat162float(__float2bfloat16_rn(wb));
  float hc = __bfloat162float(__float2bfloat16_rn(wc));
  float hd = __bfloat162float(__float2bfloat16_rn(wd));
  u32 bh0 = pack_bf16x2(wa, wb);
  u32 bh1 = pack_bf16x2(wc, wd);
  u32 bl0 = pack_bf16x2(wa - ha, wb - hb);
  u32 bl1 = pack_bf16x2(wc - hc, wd - hd);
  g_Wfrag[i] = make_float4(__uint_as_float(bh0), __uint_as_float(bh1),
                           __uint_as_float(bl0), __uint_as_float(bl1));
}

// Warp grid (R8): mt = warp>>2 (16 rows), wg = warp&3 (48 cols = 6 n-tiles).
__device__ __forceinline__ void gemm_core(const u32* __restrict__ sAhi,
                                          const u32* __restrict__ sAlo,
                                          const float4* __restrict__ wf,
                                          float acc[6][4], int tid) {
  const int warp = tid >> 5, lane = tid & 31;
  const int g = lane >> 2, tig = lane & 3;
  const int mt = warp >> 2, wg = warp & 3;
  const int r0 = mt * 16 + g;
#pragma unroll
  for (int j = 0; j < 6; j++)
#pragma unroll
    for (int q = 0; q < 4; q++) acc[j][q] = 0.0f;

  const float4* wfb = wf + (wg * 6) * (KCH * 32) + lane;
  float4 bf[6];
#pragma unroll
  for (int j = 0; j < 6; j++) bf[j] = wfb[j * (KCH * 32)];

  const u32* hp = sAhi + r0 * AST + tig;
  const u32* lp = sAlo + r0 * AST + tig;
#pragma unroll
  for (int kc = 0; kc < KCH; kc++) {
    u32 ah[4], al[4];
    ah[0] = hp[kc * 8];
    ah[1] = hp[8 * AST + kc * 8];
    ah[2] = hp[kc * 8 + 4];
    ah[3] = hp[8 * AST + kc * 8 + 4];
    al[0] = lp[kc * 8];
    al[1] = lp[8 * AST + kc * 8];
    al[2] = lp[kc * 8 + 4];
    al[3] = lp[8 * AST + kc * 8 + 4];

    float4 cur[6];
#pragma unroll
    for (int j = 0; j < 6; j++) cur[j] = bf[j];
    int kn = (kc + 1 < KCH) ? kc + 1 : 0;  // harmless wrap prefetch
#pragma unroll
    for (int j = 0; j < 6; j++) bf[j] = wfb[j * (KCH * 32) + kn * 32];
#pragma unroll
    for (int j = 0; j < 6; j++) {
      u32 bh0 = __float_as_uint(cur[j].x);
      u32 bh1 = __float_as_uint(cur[j].y);
      u32 bl0 = __float_as_uint(cur[j].z);
      u32 bl1 = __float_as_uint(cur[j].w);
      mma_bf16(acc[j], ah[0], ah[1], ah[2], ah[3], bh0, bh1);
      mma_bf16(acc[j], ah[0], ah[1], ah[2], ah[3], bl0, bl1);
      mma_bf16(acc[j], al[0], al[1], al[2], al[3], bh0, bh1);
    }
  }
}

__device__ __forceinline__ void gemm_to_smem(const u32* __restrict__ sAhi,
                                             const u32* __restrict__ sAlo,
                                             const float4* __restrict__ wf,
                                             const float* __restrict__ bias,
                                             float* __restrict__ dst, int tid) {
  float acc[6][4];
  gemm_core(sAhi, sAlo, wf, acc, tid);
  const int warp = tid >> 5, lane = tid & 31;
  const int g = lane >> 2, tig = lane & 3;
  const int mt = warp >> 2, wg = warp & 3;
  const int r0 = mt * 16 + g;
#pragma unroll
  for (int j = 0; j < 6; j++) {
    const int c = wg * 48 + 8 * j + 2 * tig;
    float2 bj = *(const float2*)(bias + c);
    *(float2*)(dst + r0 * STR + c) =
        make_float2(acc[j][0] + bj.x, acc[j][1] + bj.y);
    *(float2*)(dst + (r0 + 8) * STR + c) =
        make_float2(acc[j][2] + bj.x, acc[j][3] + bj.y);
  }
}

__device__ __forceinline__ void gemm_skip_out(const u32* __restrict__ sAhi,
                                              const u32* __restrict__ sAlo,
                                              const float4* __restrict__ wf,
                                              const float* __restrict__ bias,
                                              const float* __restrict__ sAttn,
                                              float* __restrict__ out,
                                              int b, int h0, int w0, int tid) {
  float acc[6][4];
  gemm_core(sAhi, sAlo, wf, acc, tid);
  const int warp = tid >> 5, lane = tid & 31;
  const int g = lane >> 2, tig = lane & 3;
  const int mt = warp >> 2, wg = warp & 3;
  const int r0 = mt * 16 + g;       // node (nh=2mt,   nw=g)
  const int r1 = r0 + 8;            // node (nh=2mt+1, nw=g)
  const long hw0 = (long)(h0 + 2 * mt) * Wc + w0 + g;
  const long hw1 = hw0 + Wc;
#pragma unroll
  for (int j = 0; j < 6; j++) {
    const int c = wg * 48 + 8 * j + 2 * tig;
    float2 bj = *(const float2*)(bias + c);
    float v00 = acc[j][0] + bj.x + sAttn[r0 * STR + c];
    float v01 = acc[j][1] + bj.y + sAttn[r0 * STR + c + 1];
    float v10 = acc[j][2] + bj.x + sAttn[r1 * STR + c];
    float v11 = acc[j][3] + bj.y + sAttn[r1 * STR + c + 1];
    float* base0 = out + (long)(b * Cc + c) * Hc * Wc;
    float* base1 = out + (long)(b * Cc + c + 1) * Hc * Wc;
    base0[hw0] = v00; base1[hw0] = v01;
    base0[hw1] = v10; base1[hw1] = v11;
  }
}

__global__ void __launch_bounds__(NT, 1)
wg_kernel(const float* __restrict__ x,
          const float* __restrict__ bq, const float* __restrict__ bk,
          const float* __restrict__ bv, const float* __restrict__ bsk,
          float* __restrict__ out) {
  extern __shared__ float sm[];
  float* sXW = sm;               // exact fp32 xw; bf16-hi pairs after split
  float* sQ = sXW + XW_FLOATS;
  float* sK = sQ + XW_FLOATS;
  float* sV = sK + XW_FLOATS;
  u32* sLo = (u32*)(sV + XW_FLOATS);  // 6400 u32; first 4096 alias Gram
  float* sG = (float*)sLo;            // Gram (dead after KNN)
  float* sSq = (float*)(sLo + LO_U32);   // 64 floats
  int* sIdx = (int*)(sSq + NN);          // 64*9 ints
  u32* sAhi = (u32*)sXW;                 // bf16-hi pairs, stride AST

  const int tid = threadIdx.x;
  const int w = blockIdx.x;
  const int b = w / (NWH * NWW);
  const int rem = w - b * (NWH * NWW);
  const int wh = rem / NWW, ww = rem - wh * NWW;
  const int h0 = wh * WS, w0 = ww * WS;

  // ---- Phase A: gather window nodes ----
#pragma unroll
  for (int i = 0; i < 3; i++) {
    int t = tid + NT * i;          // 0..1535 : (c, nh)
    int c = t >> 3, nh = t & 7;
    const float* src = x + ((b * Cc + c) * Hc + h0 + nh) * Wc + w0;
    float4 v0 = *(const float4*)src;
    float4 v1 = *(const float4*)(src + 4);
    float* d = sXW + (nh * 8) * STR + c;
    d[0 * STR] = v0.x; d[1 * STR] = v0.y; d[2 * STR] = v0.z; d[3 * STR] = v0.w;
    d[4 * STR] = v1.x; d[5 * STR] = v1.y; d[6 * STR] = v1.z; d[7 * STR] = v1.w;
  }
  __syncthreads();

  // ---- Phase B1: Gram matrix (exact fp32), ALL 512 threads, 2x4 tiles ----
  // rows {tn, tn+32} (tn = tid>>4), cols {tm+16j} (tm = tid&15).
  {
    const int tn = tid >> 4;        // 0..31
    const int tm = tid & 15;
    u64 acc2[2][4] = {};
#pragma unroll 2
    for (int k = 0; k < Cc; k += 4) {
      ulonglong2 a[2], bb[4];
#pragma unroll
      for (int i = 0; i < 2; i++)
        a[i] = *(const ulonglong2*)(sXW + (tn + 32 * i) * STR + k);
#pragma unroll
      for (int j = 0; j < 4; j++)
        bb[j] = *(const ulonglong2*)(sXW + (tm + 16 * j) * STR + k);
#pragma unroll
      for (int i = 0; i < 2; i++)
#pragma unroll
        for (int j = 0; j < 4; j++) {
          fma2(acc2[i][j], a[i].x, bb[j].x);
          fma2(acc2[i][j], a[i].y, bb[j].y);
        }
    }
#pragma unroll
    for (int i = 0; i < 2; i++)
#pragma unroll
      for (int j = 0; j < 4; j++)
        sG[(tn + 32 * i) * NN + tm + 16 * j] = hsum2(acc2[i][j]);
  }
  __syncthreads();
  if (tid < NN) sSq[tid] = sG[tid * (NN + 1)];
  __syncthreads();

  // ---- Phase B2: top-9 KNN, 8 lanes per node (512 threads) ----
  // Exact serial semantics: float '<' order, lowest index wins ties,
  // via lexicographic u64 min on (ordf(d) << 32 | m).
  {
    const int n = tid >> 3;         // node 0..63
    const int sub = tid & 7;        // lane within node group
    const float sqn = sSq[n];
    const float* grow = sG + n * NN;
    float dv[8];
#pragma unroll
    for (int t = 0; t < 8; t++) {
      int m = sub + 8 * t;
      float d = sqn + sSq[m] - 2.0f * grow[m];
      dv[t] = (m == n) ? 3.9e38f : d;   // exclude self
    }
    u64 mask = 0;
#pragma unroll 1
    for (int kk = 0; kk < KK; kk++) {
      u64 best = ~0ull;
#pragma unroll
      for (int t = 0; t < 8; t++) {
        int m = sub + 8 * t;
        float d = ((mask >> m) & 1ull) ? 3.9e38f : dv[t];
        u64 key = ((u64)ordf(d) << 32) | (u32)m;
        best = (key < best) ? key : best;
      }
      best = min(best, __shfl_xor_sync(0xffffffffu, best, 1));
      best = min(best, __shfl_xor_sync(0xffffffffu, best, 2));
      best = min(best, __shfl_xor_sync(0xffffffffu, best, 4));
      int bi = (int)(best & 63ull);
      mask |= 1ull << bi;
      if (sub == 0) sIdx[n * KK + kk] = bi;
    }
  }
  __syncthreads();  // KNN done reading sG before sLo overwrites it

  // ---- Phase B3: split xw -> bf16 hi pairs (over sXW) + bf16 lo pairs ----
  {
    u32 hbuf[12], lbuf[12];
#pragma unroll
    for (int i = 0; i < 12; i++) {
      int p = tid + NT * i;         // 0..6143
      int row = p / 96, idx = p - row * 96;
      const float* xr = sXW + row * STR;
      float f0 = xr[2 * idx], f1 = xr[2 * idx + 1];
      float h0 = __bfloat162float(__float2bfloat16_rn(f0));
      float h1 = __bfloat162float(__float2bfloat16_rn(f1));
      hbuf[i] = pack_bf16x2(f0, f1);
      lbuf[i] = pack_bf16x2(f0 - h0, f1 - h1);
    }
    __syncthreads();  // all fp32 reads done before overwriting
#pragma unroll
    for (int i = 0; i < 12; i++) {
      int p = tid + NT * i;
      int row = p / 96, idx = p - row * 96;
      sAhi[row * AST + idx] = hbuf[i];
      sLo[row * AST + idx] = lbuf[i];
    }
  }
  __syncthreads();

  // ---- Phase C: Q, K, V projections (bf16 tensor core, barrier-free) ----
  gemm_to_smem(sAhi, sLo, g_Wfrag + 0 * FRAG_PER_MAT, bq, sQ, tid);
  gemm_to_smem(sAhi, sLo, g_Wfrag + 1 * FRAG_PER_MAT, bk, sK, tid);
  gemm_to_smem(sAhi, sLo, g_Wfrag + 2 * FRAG_PER_MAT, bv, sV, tid);
  __syncthreads();  // sQ/sK/sV visible before attention

  // ---- Phase D: 9-neighbor softmax attention; 512 thr = one (n,h) each ----
  {
    const int n = tid & (NN - 1);
    const int h = tid >> 6;
    const float* qp = sQ + n * STR + h * DH;
    float q[DH];
#pragma unroll
    for (int d4 = 0; d4 < DH / 4; d4++) {
      float4 v = *(const float4*)(qp + d4 * 4);
      q[d4 * 4 + 0] = v.x; q[d4 * 4 + 1] = v.y;
      q[d4 * 4 + 2] = v.z; q[d4 * 4 + 3] = v.w;
    }
    float sc[KK];
    int nb[KK];
#pragma unroll
    for (int kk = 0; kk < KK; kk++) {
      int m = sIdx[n * KK + kk];
      nb[kk] = m;
      const float* kp = sK + m * STR + h * DH;
      float s = 0.0f;
#pragma unroll
      for (int d4 = 0; d4 < DH / 4; d4++) {
        float4 v = *(const float4*)(kp + d4 * 4);
        s = fmaf(q[d4 * 4 + 0], v.x, s);
        s = fmaf(q[d4 * 4 + 1], v.y, s);
        s = fmaf(q[d4 * 4 + 2], v.z, s);
        s = fmaf(q[d4 * 4 + 3], v.w, s);
      }
      sc[kk] = s * INV_SQRT_DH;
    }
    float mx = sc[0];
#pragma unroll
    for (int kk = 1; kk < KK; kk++) mx = fmaxf(mx, sc[kk]);
    float ssum = 0.0f;
#pragma unroll
    for (int kk = 0; kk < KK; kk++) { sc[kk] = __expf(sc[kk] - mx); ssum += sc[kk]; }
    const float inv = 1.0f / ssum;
    float o[DH] = {};
#pragma unroll
    for (int kk = 0; kk < KK; kk++) {
      float a = sc[kk] * inv;
      const float* vp = sV + nb[kk] * STR + h * DH;
#pragma unroll
      for (int d4 = 0; d4 < DH / 4; d4++) {
        float4 v = *(const float4*)(vp + d4 * 4);
        o[d4 * 4 + 0] = fmaf(a, v.x, o[d4 * 4 + 0]);
        o[d4 * 4 + 1] = fmaf(a, v.y, o[d4 * 4 + 1]);
        o[d4 * 4 + 2] = fmaf(a, v.z, o[d4 * 4 + 2]);
        o[d4 * 4 + 3] = fmaf(a, v.w, o[d4 * 4 + 3]);
      }
    }
    float* op = sQ + n * STR + h * DH;  // attn out overwrites own q segment
#pragma unroll
    for (int d4 = 0; d4 < DH / 4; d4++)
      *(float4*)(op + d4 * 4) =
          make_float4(o[d4 * 4 + 0], o[d4 * 4 + 1], o[d4 * 4 + 2], o[d4 * 4 + 3]);
  }
  __syncthreads();  // attn results in sQ visible before skip epilogue reads

  // ---- Phase E: skip GEMM + attn add + scatter to [B,C,H,W] ----
  gemm_skip_out(sAhi, sLo, g_Wfrag + 3 * FRAG_PER_MAT, bsk, sQ, out,
                b, h0, w0, tid);
}

extern "C" void kernel_launch(void* const* d_in, const int* in_sizes, int n_in,
                              void* d_out, int out_size) {
  const float* x   = (const float*)d_in[0];
  const float* Wq  = (const float*)d_in[1];
  const float* bq  = (const float*)d_in[2];
  const float* Wk  = (const float*)d_in[3];
  const float* bk  = (const float*)d_in[4];
  const float* Wv  = (const float*)d_in[5];
  const float* bv  = (const float*)d_in[6];
  const float* Wsk = (const float*)d_in[7];
  const float* bsk = (const float*)d_in[8];
  float* out = (float*)d_out;

  pack_w_kernel<<<(4 * FRAG_PER_MAT + 255) / 256, 256>>>(Wq, Wk, Wv, Wsk);

  cudaFuncSetAttribute(wg_kernel, cudaFuncAttributeMaxDynamicSharedMemorySize,
                       (int)SMEM_BYTES);
  wg_kernel<<<WB, NT, SMEM_BYTES>>>(x, bq, bk, bv, bsk, out);
}

// round 17
// speedup vs baseline: 1.6863x; 1.0712x over previous
#include <cuda_runtime.h>
#include <cuda_bf16.h>

// ---------------------------------------------------------------------------
// WindowGrapherPyg fused kernel, R16: zero-redundancy B fetch.
// Phase C/E restructured into two fused passes (Q|K, then V|skip): each warp
// computes ALL 64 rows x 3 n-tiles of one matrix half, so every pre-packed
// B fragment is loaded exactly once per CTA (4x less B LDG than R15).
// Skip accs stashed (+bias) into dead A-hi smem; final parallel epilogue
// adds attention + skip and scatters to [B,C,H,W].
// GEMM math (2xBF16 3-product m16n8k16) bit-identical to R15.
// ---------------------------------------------------------------------------

typedef unsigned long long u64;
typedef unsigned int u32;

namespace {
constexpr int Bc = 2, Cc = 192, Hc = 192, Wc = 192;
constexpr int WS = 8, NN = 64, KK = 9, HEADS = 8, DH = 24;
constexpr int NWH = Hc / WS, NWW = Wc / WS;         // 24 x 24
constexpr int WB = Bc * NWH * NWW;                  // 1152 windows
constexpr int STR = 196;                            // row stride (floats)
constexpr int NT = 512;
constexpr int XW_FLOATS = NN * STR;                 // 12544 = 64*196 exactly
constexpr int NTILES = Cc / 8;                      // 24 n-tiles per matrix
constexpr int KCH = Cc / 16;                        // 12 k16-chunks
constexpr int FRAG_PER_MAT = NTILES * KCH * 32;     // 9216 float4
constexpr int AST = 100;                            // A hi/lo row stride (u32)
constexpr int LO_U32 = NN * AST;                    // 6400 (>= 4096 Gram alias)
constexpr size_t SMEM_BYTES =
    (size_t)(4 * XW_FLOATS + LO_U32 + NN) * sizeof(float) +
    (size_t)(NN * KK) * sizeof(int);                // 228,864 B
constexpr float INV_SQRT_DH = 0.20412414523193154f;
}

// Pre-packed bf16 hi/lo B fragments: [mat][ntile][kchunk][lane] float4
__device__ float4 g_Wfrag[4 * FRAG_PER_MAT];

__device__ __forceinline__ void fma2(u64& d, u64 a, u64 b) {
  asm("fma.rn.f32x2 %0, %1, %2, %0;" : "+l"(d) : "l"(a), "l"(b));
}
__device__ __forceinline__ float hsum2(u64 v) {
  float2 o; asm("mov.b64 {%0, %1}, %2;" : "=f"(o.x), "=f"(o.y) : "l"(v));
  return o.x + o.y;
}
__device__ __forceinline__ u32 pack_bf16x2(float lo_k, float hi_k) {
  u32 a = (u32)__bfloat16_as_ushort(__float2bfloat16_rn(lo_k));
  u32 b = (u32)__bfloat16_as_ushort(__float2bfloat16_rn(hi_k));
  return a | (b << 16);
}
__device__ __forceinline__ u32 ordf(float f) {
  u32 b = __float_as_uint(f);
  return b ^ ((b >> 31) ? 0xFFFFFFFFu : 0x80000000u);
}
__device__ __forceinline__ void mma_bf16(float d[4], u32 a0, u32 a1,
                                         u32 a2, u32 a3, u32 b0, u32 b1) {
  asm("mma.sync.aligned.m16n8k16.row.col.f32.bf16.bf16.f32 "
      "{%0,%1,%2,%3}, {%4,%5,%6,%7}, {%8,%9}, {%0,%1,%2,%3};"
      : "+f"(d[0]), "+f"(d[1]), "+f"(d[2]), "+f"(d[3])
      : "r"(a0), "r"(a1), "r"(a2), "r"(a3), "r"(b0), "r"(b1));
}

// Prologue: split W into bf16 hi/lo and pack per-lane k16 fragments.
__global__ void pack_w_kernel(const float* __restrict__ w0,
                              const float* __restrict__ w1,
                              const float* __restrict__ w2,
                              const float* __restrict__ w3) {
  int i = blockIdx.x * blockDim.x + threadIdx.x;
  if (i >= 4 * FRAG_PER_MAT) return;
  int lane = i & 31;
  int t = i >> 5;
  int kc = t % KCH; t /= KCH;
  int ntile = t % NTILES;
  int mat = t / NTILES;
  const float* W = (mat == 0) ? w0 : (mat == 1) ? w1 : (mat == 2) ? w2 : w3;
  int g = lane >> 2, tig = lane & 3;
  int n = ntile * 8 + g;
  int k0 = kc * 16 + 2 * tig;
  float wa = W[(k0 + 0) * Cc + n], wb = W[(k0 + 1) * Cc + n];
  float wc = W[(k0 + 8) * Cc + n], wd = W[(k0 + 9) * Cc + n];
  float ha = __bfloat162float(__float2bfloat16_rn(wa));
  float hb = __bfloat162float(__float2bfloat16_rn(wb));
  float hc = __bfloat162float(__float2bfloat16_rn(wc));
  float hd = __bfloat162float(__float2bfloat16_rn(wd));
  u32 bh0 = pack_bf16x2(wa, wb);
  u32 bh1 = pack_bf16x2(wc, wd);
  u32 bl0 = pack_bf16x2(wa - ha, wb - hb);
  u32 bl1 = pack_bf16x2(wc - hc, wd - hd);
  g_Wfrag[i] = make_float4(__uint_as_float(bh0), __uint_as_float(bh1),
                           __uint_as_float(bl0), __uint_as_float(bl1));
}

// Fused GEMM: one warp computes ALL 64 rows x 3 n-tiles of one matrix.
// wf must point at the warp's 3-ntile fragment base (+lane added here).
__device__ __forceinline__ void gemm64_core(const u32* __restrict__ sAhi,
                                            const u32* __restrict__ sAlo,
                                            const float4* __restrict__ wf,
                                            float acc[4][3][4], int lane) {
  const int g = lane >> 2, tig = lane & 3;
#pragma unroll
  for (int mt = 0; mt < 4; mt++)
#pragma unroll
    for (int j = 0; j < 3; j++)
#pragma unroll
      for (int q = 0; q < 4; q++) acc[mt][j][q] = 0.0f;

  const float4* wfb = wf + lane;
  float4 bf[3];
#pragma unroll
  for (int j = 0; j < 3; j++) bf[j] = wfb[j * (KCH * 32)];

  const u32* hp = sAhi + g * AST + tig;
  const u32* lp = sAlo + g * AST + tig;
#pragma unroll
  for (int kc = 0; kc < KCH; kc++) {
    u32 ah[4][4], al[4][4];
#pragma unroll
    for (int mt = 0; mt < 4; mt++) {
      const u32* h = hp + (mt * 16) * AST + kc * 8;
      const u32* l = lp + (mt * 16) * AST + kc * 8;
      ah[mt][0] = h[0];
      ah[mt][1] = h[8 * AST];
      ah[mt][2] = h[4];
      ah[mt][3] = h[8 * AST + 4];
      al[mt][0] = l[0];
      al[mt][1] = l[8 * AST];
      al[mt][2] = l[4];
      al[mt][3] = l[8 * AST + 4];
    }
    float4 cur[3];
#pragma unroll
    for (int j = 0; j < 3; j++) cur[j] = bf[j];
    int kn = (kc + 1 < KCH) ? kc + 1 : 0;  // harmless wrap prefetch
#pragma unroll
    for (int j = 0; j < 3; j++) bf[j] = wfb[j * (KCH * 32) + kn * 32];
#pragma unroll
    for (int j = 0; j < 3; j++) {
      u32 bh0 = __float_as_uint(cur[j].x);
      u32 bh1 = __float_as_uint(cur[j].y);
      u32 bl0 = __float_as_uint(cur[j].z);
      u32 bl1 = __float_as_uint(cur[j].w);
#pragma unroll
      for (int mt = 0; mt < 4; mt++) {
        mma_bf16(acc[mt][j], ah[mt][0], ah[mt][1], ah[mt][2], ah[mt][3], bh0, bh1);
        mma_bf16(acc[mt][j], ah[mt][0], ah[mt][1], ah[mt][2], ah[mt][3], bl0, bl1);
        mma_bf16(acc[mt][j], al[mt][0], al[mt][1], al[mt][2], al[mt][3], bh0, bh1);
      }
    }
  }
}

// Store a 64x24 warp tile (+bias) into an STR-stride smem buffer.
__device__ __forceinline__ void store_tile(const float acc[4][3][4],
                                           const float* __restrict__ bias,
                                           float* __restrict__ dst,
                                           int wgi, int lane) {
  const int g = lane >> 2, tig = lane & 3;
#pragma unroll
  for (int mt = 0; mt < 4; mt++) {
    const int r0 = mt * 16 + g;
#pragma unroll
    for (int j = 0; j < 3; j++) {
      const int c = wgi * 24 + 8 * j + 2 * tig;
      float2 bj = *(const float2*)(bias + c);
      *(float2*)(dst + r0 * STR + c) =
          make_float2(acc[mt][j][0] + bj.x, acc[mt][j][1] + bj.y);
      *(float2*)(dst + (r0 + 8) * STR + c) =
          make_float2(acc[mt][j][2] + bj.x, acc[mt][j][3] + bj.y);
    }
  }
}

__global__ void __launch_bounds__(NT, 1)
wg_kernel(const float* __restrict__ x,
          const float* __restrict__ bq, const float* __restrict__ bk,
          const float* __restrict__ bv, const float* __restrict__ bsk,
          float* __restrict__ out) {
  extern __shared__ float sm[];
  float* sXW = sm;               // fp32 xw -> A-hi pairs -> skip stash
  float* sQ = sXW + XW_FLOATS;
  float* sK = sQ + XW_FLOATS;
  float* sV = sK + XW_FLOATS;
  u32* sLo = (u32*)(sV + XW_FLOATS);  // 6400 u32; first 4096 alias Gram
  float* sG = (float*)sLo;            // Gram (dead after KNN)
  float* sSq = (float*)(sLo + LO_U32);   // 64 floats
  int* sIdx = (int*)(sSq + NN);          // 64*9 ints
  u32* sAhi = (u32*)sXW;                 // bf16-hi pairs, stride AST
  float* sSkip = sXW;                    // skip result, stride STR (post-P2)

  const int tid = threadIdx.x;
  const int warp = tid >> 5, lane = tid & 31;
  const int w = blockIdx.x;
  const int b = w / (NWH * NWW);
  const int rem = w - b * (NWH * NWW);
  const int wh = rem / NWW, ww = rem - wh * NWW;
  const int h0 = wh * WS, w0 = ww * WS;

  // ---- Phase A: gather window nodes ----
#pragma unroll
  for (int i = 0; i < 3; i++) {
    int t = tid + NT * i;          // 0..1535 : (c, nh)
    int c = t >> 3, nh = t & 7;
    const float* src = x + ((b * Cc + c) * Hc + h0 + nh) * Wc + w0;
    float4 v0 = *(const float4*)src;
    float4 v1 = *(const float4*)(src + 4);
    float* d = sXW + (nh * 8) * STR + c;
    d[0 * STR] = v0.x; d[1 * STR] = v0.y; d[2 * STR] = v0.z; d[3 * STR] = v0.w;
    d[4 * STR] = v1.x; d[5 * STR] = v1.y; d[6 * STR] = v1.z; d[7 * STR] = v1.w;
  }
  __syncthreads();

  // ---- Phase B1: Gram matrix (exact fp32), ALL 512 threads, 2x4 tiles ----
  {
    const int tn = tid >> 4;        // 0..31
    const int tm = tid & 15;
    u64 acc2[2][4] = {};
#pragma unroll 2
    for (int k = 0; k < Cc; k += 4) {
      ulonglong2 a[2], bb[4];
#pragma unroll
      for (int i = 0; i < 2; i++)
        a[i] = *(const ulonglong2*)(sXW + (tn + 32 * i) * STR + k);
#pragma unroll
      for (int j = 0; j < 4; j++)
        bb[j] = *(const ulonglong2*)(sXW + (tm + 16 * j) * STR + k);
#pragma unroll
      for (int i = 0; i < 2; i++)
#pragma unroll
        for (int j = 0; j < 4; j++) {
          fma2(acc2[i][j], a[i].x, bb[j].x);
          fma2(acc2[i][j], a[i].y, bb[j].y);
        }
    }
#pragma unroll
    for (int i = 0; i < 2; i++)
#pragma unroll
      for (int j = 0; j < 4; j++)
        sG[(tn + 32 * i) * NN + tm + 16 * j] = hsum2(acc2[i][j]);
  }
  __syncthreads();
  if (tid < NN) sSq[tid] = sG[tid * (NN + 1)];
  __syncthreads();

  // ---- Phase B2: top-9 KNN, 8 lanes per node (exact serial semantics) ----
  {
    const int n = tid >> 3;
    const int sub = tid & 7;
    const float sqn = sSq[n];
    const float* grow = sG + n * NN;
    float dv[8];
#pragma unroll
    for (int t = 0; t < 8; t++) {
      int m = sub + 8 * t;
      float d = sqn + sSq[m] - 2.0f * grow[m];
      dv[t] = (m == n) ? 3.9e38f : d;
    }
    u64 mask = 0;
#pragma unroll 1
    for (int kk = 0; kk < KK; kk++) {
      u64 best = ~0ull;
#pragma unroll
      for (int t = 0; t < 8; t++) {
        int m = sub + 8 * t;
        float d = ((mask >> m) & 1ull) ? 3.9e38f : dv[t];
        u64 key = ((u64)ordf(d) << 32) | (u32)m;
        best = (key < best) ? key : best;
      }
      best = min(best, __shfl_xor_sync(0xffffffffu, best, 1));
      best = min(best, __shfl_xor_sync(0xffffffffu, best, 2));
      best = min(best, __shfl_xor_sync(0xffffffffu, best, 4));
      int bi = (int)(best & 63ull);
      mask |= 1ull << bi;
      if (sub == 0) sIdx[n * KK + kk] = bi;
    }
  }
  __syncthreads();  // KNN done reading sG before sLo overwrites it

  // ---- Phase B3: split xw -> bf16 hi pairs (over sXW) + bf16 lo pairs ----
  {
    u32 hbuf[12], lbuf[12];
#pragma unroll
    for (int i = 0; i < 12; i++) {
      int p = tid + NT * i;         // 0..6143
      int row = p / 96, idx = p - row * 96;
      const float* xr = sXW + row * STR;
      float f0 = xr[2 * idx], f1 = xr[2 * idx + 1];
      float h0 = __bfloat162float(__float2bfloat16_rn(f0));
      float h1 = __bfloat162float(__float2bfloat16_rn(f1));
      hbuf[i] = pack_bf16x2(f0, f1);
      lbuf[i] = pack_bf16x2(f0 - h0, f1 - h1);
    }
    __syncthreads();  // all fp32 reads done before overwriting
#pragma unroll
    for (int i = 0; i < 12; i++) {
      int p = tid + NT * i;
      int row = p / 96, idx = p - row * 96;
      sAhi[row * AST + idx] = hbuf[i];
      sLo[row * AST + idx] = lbuf[i];
    }
  }
  __syncthreads();

  const int wgi = warp & 7;
  const int half = warp >> 3;     // 0 or 1

  // ---- Pass 1: Q (warps 0-7) | K (warps 8-15), each B frag loaded once ----
  {
    const float4* wf = g_Wfrag + half * FRAG_PER_MAT + (wgi * 3) * (KCH * 32);
    float acc[4][3][4];
    gemm64_core(sAhi, sLo, wf, acc, lane);
    store_tile(acc, half ? bk : bq, half ? sK : sQ, wgi, lane);
  }

  // ---- Pass 2: V (warps 0-7) | skip (warps 8-15) ----
  float accS[4][3][4];
  {
    const float4* wf =
        g_Wfrag + (2 + half) * FRAG_PER_MAT + (wgi * 3) * (KCH * 32);
    gemm64_core(sAhi, sLo, wf, accS, lane);
    if (half == 0) store_tile(accS, bv, sV, wgi, lane);
  }
  __syncthreads();  // all GEMMs done: sQ/sK/sV complete, sAhi/sLo dead

  // ---- Stash skip (+bias) into dead A-hi region (64x196 fits exactly) ----
  if (half == 1) store_tile(accS, bsk, sSkip, wgi, lane);

  // ---- Phase D: 9-neighbor softmax attention; 512 thr = one (n,h) each ----
  {
    const int n = tid & (NN - 1);
    const int h = tid >> 6;
    const float* qp = sQ + n * STR + h * DH;
    float q[DH];
#pragma unroll
    for (int d4 = 0; d4 < DH / 4; d4++) {
      float4 v = *(const float4*)(qp + d4 * 4);
      q[d4 * 4 + 0] = v.x; q[d4 * 4 + 1] = v.y;
      q[d4 * 4 + 2] = v.z; q[d4 * 4 + 3] = v.w;
    }
    float sc[KK];
    int nb[KK];
#pragma unroll
    for (int kk = 0; kk < KK; kk++) {
      int m = sIdx[n * KK + kk];
      nb[kk] = m;
      const float* kp = sK + m * STR + h * DH;
      float s = 0.0f;
#pragma unroll
      for (int d4 = 0; d4 < DH / 4; d4++) {
        float4 v = *(const float4*)(kp + d4 * 4);
        s = fmaf(q[d4 * 4 + 0], v.x, s);
        s = fmaf(q[d4 * 4 + 1], v.y, s);
        s = fmaf(q[d4 * 4 + 2], v.z, s);
        s = fmaf(q[d4 * 4 + 3], v.w, s);
      }
      sc[kk] = s * INV_SQRT_DH;
    }
    float mx = sc[0];
#pragma unroll
    for (int kk = 1; kk < KK; kk++) mx = fmaxf(mx, sc[kk]);
    float ssum = 0.0f;
#pragma unroll
    for (int kk = 0; kk < KK; kk++) { sc[kk] = __expf(sc[kk] - mx); ssum += sc[kk]; }
    const float inv = 1.0f / ssum;
    float o[DH] = {};
#pragma unroll
    for (int kk = 0; kk < KK; kk++) {
      float a = sc[kk] * inv;
      const float* vp = sV + nb[kk] * STR + h * DH;
#pragma unroll
      for (int d4 = 0; d4 < DH / 4; d4++) {
        float4 v = *(const float4*)(vp + d4 * 4);
        o[d4 * 4 + 0] = fmaf(a, v.x, o[d4 * 4 + 0]);
        o[d4 * 4 + 1] = fmaf(a, v.y, o[d4 * 4 + 1]);
        o[d4 * 4 + 2] = fmaf(a, v.z, o[d4 * 4 + 2]);
        o[d4 * 4 + 3] = fmaf(a, v.w, o[d4 * 4 + 3]);
      }
    }
    float* op = sQ + n * STR + h * DH;  // attn out overwrites own q segment
#pragma unroll
    for (int d4 = 0; d4 < DH / 4; d4++)
      *(float4*)(op + d4 * 4) =
          make_float4(o[d4 * 4 + 0], o[d4 * 4 + 1], o[d4 * 4 + 2], o[d4 * 4 + 3]);
  }
  __syncthreads();  // attn (sQ) + skip stash (sSkip) visible to all

  // ---- Phase E: out = skip + attn, coalesced-ish scatter to [B,C,H,W] ----
  {
    const int n = tid & (NN - 1);   // node
    const int cg = tid >> 6;        // 0..7 -> cols 24cg..24cg+23
    const int nh = n >> 3, nw = n & 7;
    const float* sp = sSkip + n * STR + cg * 24;
    const float* ap = sQ + n * STR + cg * 24;
    const long hw = (long)(h0 + nh) * Wc + w0 + nw;
#pragma unroll
    for (int j = 0; j < 6; j++) {
      float4 s = *(const float4*)(sp + 4 * j);
      float4 a = *(const float4*)(ap + 4 * j);
      const int c = cg * 24 + 4 * j;
      out[(long)(b * Cc + c + 0) * Hc * Wc + hw] = s.x + a.x;
      out[(long)(b * Cc + c + 1) * Hc * Wc + hw] = s.y + a.y;
      out[(long)(b * Cc + c + 2) * Hc * Wc + hw] = s.z + a.z;
      out[(long)(b * Cc + c + 3) * Hc * Wc + hw] = s.w + a.w;
    }
  }
}

extern "C" void kernel_launch(void* const* d_in, const int* in_sizes, int n_in,
                              void* d_out, int out_size) {
  const float* x   = (const float*)d_in[0];
  const float* Wq  = (const float*)d_in[1];
  const float* bq  = (const float*)d_in[2];
  const float* Wk  = (const float*)d_in[3];
  const float* bk  = (const float*)d_in[4];
  const float* Wv  = (const float*)d_in[5];
  const float* bv  = (const float*)d_in[6];
  const float* Wsk = (const float*)d_in[7];
  const float* bsk = (const float*)d_in[8];
  float* out = (float*)d_out;

  pack_w_kernel<<<(4 * FRAG_PER_MAT + 255) / 256, 256>>>(Wq, Wk, Wv, Wsk);

  cudaFuncSetAttribute(wg_kernel, cudaFuncAttributeMaxDynamicSharedMemorySize,
                       (int)SMEM_BYTES);
  wg_kernel<<<WB, NT, SMEM_BYTES>>>(x, bq, bk, bv, bsk, out);
}